// round 8
// baseline (speedup 1.0000x reference)
#include <cuda_runtime.h>
#include <math.h>
#include <stdint.h>

#define B_ROWS 4096
#define DIM    512
#define NCLS   31
#define NTOT   8192
#define NT     32        // 4096/128 tiles per side
#define TRI    528       // NT*(NT+1)/2

typedef unsigned long long ull;

// ---------------- device scratch ----------------
__device__ double g_sumsq;
__device__ double g_acc[3];
__device__ float  g_S[DIM];
__device__ float  g_sq[NTOT];
__device__ int    g_scount[NCLS];
__device__ int    g_tcount[NCLS];
__device__ float  g_tcolsum[NCLS];
__device__ float  g_css[NCLS];
__device__ float  g_cst[NCLS];
__device__ float  g_invts[NCLS];
__device__ __align__(16) float g_u[B_ROWS * 32];
__device__ float  g_c[5];
__device__ float  g_scale;
__device__ float  g_lamb;
// precomputed TT weights (scale * <u_i,u_j>), upper-triangle tiles, [tri][128][128]
__device__ __align__(16) float g_wtt[TRI * 128 * 128];

// ---------------- init ----------------
__global__ void k_init() {
    int t = threadIdx.x;
    if (t == 0) g_sumsq = 0.0;
    if (t < 3) g_acc[t] = 0.0;
    if (t < NCLS) { g_scount[t] = 0; g_tcount[t] = 0; g_tcolsum[t] = 0.f; }
    if (t < DIM) g_S[t] = 0.f;
}

// ---------------- row squared norms ----------------
__global__ void k_sq(const float* __restrict__ src, const float* __restrict__ tgt) {
    int w = (blockIdx.x * blockDim.x + threadIdx.x) >> 5;
    int lane = threadIdx.x & 31;
    if (w >= NTOT) return;
    const float* row = (w < B_ROWS) ? (src + (size_t)w * DIM)
                                    : (tgt + (size_t)(w - B_ROWS) * DIM);
    float s = 0.f;
    for (int k = lane; k < DIM; k += 32) { float v = row[k]; s = fmaf(v, v, s); }
    #pragma unroll
    for (int o = 16; o; o >>= 1) s += __shfl_xor_sync(0xffffffffu, s, o);
    if (lane == 0) { g_sq[w] = s; atomicAdd(&g_sumsq, (double)s); }
}

// ---------------- column sums ----------------
__global__ void k_colsum(const float* __restrict__ src, const float* __restrict__ tgt) {
    int d = threadIdx.x;
    int b = blockIdx.x;
    float s = 0.f;
    int r0 = b * 128;
    for (int r = r0; r < r0 + 128; r++)
        s += src[(size_t)r * DIM + d] + tgt[(size_t)r * DIM + d];
    atomicAdd(&g_S[d], s);
}

// ---------------- class stats ----------------
__global__ void k_stats(const int* __restrict__ lbl, const float* __restrict__ logits) {
    int b = blockIdx.x;
    int t = threadIdx.x;
    int i = b * 256 + t;
    atomicAdd(&g_scount[lbl[i]], 1);
    const float* row = logits + (size_t)i * NCLS;
    float mv = row[0]; int mi = 0;
    #pragma unroll
    for (int c = 1; c < NCLS; c++) { float v = row[c]; if (v > mv) { mv = v; mi = c; } }
    atomicAdd(&g_tcount[mi], 1);
    if (t < NCLS) {
        float s = 0.f;
        for (int r = 0; r < 256; r++) s += logits[(size_t)(b * 256 + r) * NCLS + t];
        atomicAdd(&g_tcolsum[t], s);
    }
}

// ---------------- finalize ----------------
__global__ void k_finalize(const int* __restrict__ curr_iter) {
    __shared__ double sred[512];
    __shared__ float  sm[NCLS];
    __shared__ float  sscale;
    int t = threadIdx.x;
    double v = (double)g_S[t];
    sred[t] = v * v;
    __syncthreads();
    for (int o = 256; o; o >>= 1) { if (t < o) sred[t] += sred[t + o]; __syncthreads(); }
    if (t < NCLS) sm[t] = (g_scount[t] > 0 && g_tcount[t] > 0) ? 1.f : 0.f;
    __syncthreads();
    if (t == 0) {
        float cnt = 0.f;
        for (int c = 0; c < NCLS; c++) cnt += sm[c];
        sscale = (cnt > 0.f) ? 1.f / fmaxf(cnt, 1.f) : 0.f;
        g_scale = sscale;
    }
    __syncthreads();
    if (t < NCLS) {
        float m = sm[t];
        int sc = g_scount[t];
        float css = 0.f, cst = 0.f;
        if (sc > 0) { float fc = (float)sc; css = m * sscale / (fc * fc); cst = m * sscale / fc; }
        g_css[t] = css; g_cst[t] = cst;
        float ts = g_tcolsum[t]; if (ts == 0.f) ts = 100.f;
        g_invts[t] = m / ts;
    }
    if (t == 0) {
        double sumL2 = 2.0 * (double)NTOT * g_sumsq - 2.0 * sred[0];
        double bw = sumL2 / ((double)NTOT * (double)NTOT - (double)NTOT);
        bw = bw / 4.0;
        for (int i = 0; i < 5; i++)
            g_c[i] = (float)(-1.4426950408889634 / (bw * (double)(1 << i)));
        double p = (double)curr_iter[0] / 1000.0;
        g_lamb = (float)(2.0 / (1.0 + exp(-p)) - 1.0);
    }
}

// ---------------- masked normalized target logits ----------------
__global__ void k_u(const float* __restrict__ logits) {
    int i = blockIdx.x * blockDim.x + threadIdx.x;
    if (i >= B_ROWS) return;
    #pragma unroll
    for (int c = 0; c < NCLS; c++)
        g_u[i * 32 + c] = logits[(size_t)i * NCLS + c] * g_invts[c];
    g_u[i * 32 + 31] = 0.f;
}

// ---------------- precompute TT weight tiles: scale * U U^T ----------------
__global__ __launch_bounds__(256, 2)
void k_wtt() {
    __shared__ float Us[128][33];
    __shared__ float Ut[128][33];
    int bid = blockIdx.x;     // tri index
    int r = 0, b = bid;
    while (b >= NT - r) { b -= NT - r; r++; }
    int ti = r, tj = r + b;
    int gi0 = ti * 128, gj0 = tj * 128;
    int t = threadIdx.x;
    int tx = t & 15, ty = t >> 4;

    for (int idx = t; idx < 4096; idx += 256) {
        int row = idx >> 5, c = idx & 31;
        Us[row][c] = g_u[(size_t)(gi0 + row) * 32 + c];
        Ut[row][c] = g_u[(size_t)(gj0 + row) * 32 + c];
    }
    __syncthreads();

    float acc[8][8];
    #pragma unroll
    for (int i = 0; i < 8; i++)
        #pragma unroll
        for (int j = 0; j < 8; j++) acc[i][j] = 0.f;

    #pragma unroll 1
    for (int c = 0; c < NCLS; c++) {
        float a[8], bb[8];
        #pragma unroll
        for (int i = 0; i < 8; i++) a[i] = Us[ty * 8 + i][c];
        #pragma unroll
        for (int j = 0; j < 8; j++) bb[j] = Ut[tx * 8 + j][c];
        #pragma unroll
        for (int i = 0; i < 8; i++)
            #pragma unroll
            for (int j = 0; j < 8; j++)
                acc[i][j] = fmaf(a[i], bb[j], acc[i][j]);
    }

    float scale = g_scale;
    float* W = g_wtt + (size_t)bid * 16384;
    #pragma unroll
    for (int i = 0; i < 8; i++) {
        int il = ty * 8 + i;
        float4 v0 = make_float4(acc[i][0]*scale, acc[i][1]*scale, acc[i][2]*scale, acc[i][3]*scale);
        float4 v1 = make_float4(acc[i][4]*scale, acc[i][5]*scale, acc[i][6]*scale, acc[i][7]*scale);
        *(float4*)(W + il * 128 + tx * 8 + 0) = v0;
        *(float4*)(W + il * 128 + tx * 8 + 4) = v1;
    }
}

// ---------------- helpers ----------------
__device__ __forceinline__ float ex2f(float x) {
    float r; asm("ex2.approx.ftz.f32 %0, %1;" : "=f"(r) : "f"(x)); return r;
}
#define FFMA2(d, a, b) \
    asm("fma.rn.f32x2 %0, %1, %2, %0;" : "+l"(d) : "l"(a), "l"(b))
#define PACK2(d, x) \
    asm("mov.b64 %0, {%1, %1};" : "=l"(d) : "f"(x))
#define UNPACK2(lo, hi, v) \
    asm("mov.b64 {%0, %1}, %2;" : "=f"(lo), "=f"(hi) : "l"(v))

// ---------------- main fused GEMM + kernel-weight epilogue ----------------
__global__ __launch_bounds__(256, 2)
void k_main(const float* __restrict__ src, const float* __restrict__ tgt,
            const int* __restrict__ slabel) {
    __shared__ float As[2][8][256];     // DUPLICATED: As[s][k][2*row]=As[s][k][2*row+1]
    __shared__ float BP[2][8][128];     // pair-swizzled (ull idx = jp*16 + tx)
    __shared__ float sqI[128], sqJ[128];
    __shared__ int   Li[128], Lj[128];
    __shared__ float s_css[32], s_cst[32];
    __shared__ float UjT[32][128];      // type==2 only: [class][j]

    int bid = blockIdx.x;
    int type, ti, tj, triq = 0;
    if (bid < TRI) { type = 0; }
    else if (bid < 2 * TRI) { type = 1; bid -= TRI; }
    else { type = 2; bid -= 2 * TRI; }
    if (type < 2) {
        int r = 0, b = bid;
        while (b >= NT - r) { b -= NT - r; r++; }
        ti = r; tj = r + b; triq = bid;
    } else { ti = bid >> 5; tj = bid & 31; }

    const float* Xi = (type == 1) ? tgt : src;
    const float* Xj = (type == 0) ? src : tgt;
    int gi0 = ti * 128, gj0 = tj * 128;

    int t = threadIdx.x;
    int tx = t & 15, ty = t >> 4;
    int lr = t >> 1, lc = (t & 1) << 2;

    const float* pa = Xi + (size_t)(gi0 + lr) * DIM + lc;
    const float* pb = Xj + (size_t)(gj0 + lr) * DIM + lc;

    // pair-swizzle store index for B (depends only on lr)
    int pi_ = lr >> 1;
    int bfi = ((pi_ & 3) * 16 + (pi_ >> 2)) * 2 + (lr & 1);

    // ---- small-table loads ----
    if (t < 128) {
        sqI[t] = g_sq[((type == 1) ? B_ROWS : 0) + gi0 + t];
        sqJ[t] = g_sq[((type == 0) ? 0 : B_ROWS) + gj0 + t];
        if (type != 1) Li[t] = slabel[gi0 + t];
        if (type == 0) Lj[t] = slabel[gj0 + t];
    }
    if (t < NCLS) { s_css[t] = g_css[t]; s_cst[t] = g_cst[t]; }
    if (type == 2) {
        for (int idx = t; idx < 4096; idx += 256) {
            int c = idx >> 7, j = idx & 127;
            UjT[c][j] = g_u[(size_t)(gj0 + j) * 32 + c];
        }
    }

    // ---- prefetch first chunk ----
    float4 a_nx = *(const float4*)pa;
    float4 b_nx = *(const float4*)pb;

    ull acc2[8][4];
    #pragma unroll
    for (int i = 0; i < 8; i++)
        #pragma unroll
        for (int j = 0; j < 4; j++) acc2[i][j] = 0ull;

    #pragma unroll 1
    for (int c = 0; c < 64; c++) {
        int s = c & 1;
        // store current chunk: A duplicated (PACK2 once per chunk), B pair-swizzled
        {
            ull p0, p1, p2, p3;
            PACK2(p0, a_nx.x); PACK2(p1, a_nx.y);
            PACK2(p2, a_nx.z); PACK2(p3, a_nx.w);
            ((ull*)&As[s][lc + 0][0])[lr] = p0;
            ((ull*)&As[s][lc + 1][0])[lr] = p1;
            ((ull*)&As[s][lc + 2][0])[lr] = p2;
            ((ull*)&As[s][lc + 3][0])[lr] = p3;
            BP[s][lc + 0][bfi] = b_nx.x; BP[s][lc + 1][bfi] = b_nx.y;
            BP[s][lc + 2][bfi] = b_nx.z; BP[s][lc + 3][bfi] = b_nx.w;
        }
        __syncthreads();
        // prefetch next chunk (latency hidden under compute)
        if (c < 63) {
            a_nx = *(const float4*)(pa + (c + 1) * 8);
            b_nx = *(const float4*)(pb + (c + 1) * 8);
        }
        #pragma unroll
        for (int kk = 0; kk < 8; kk++) {
            const ull* brow = (const ull*)&BP[s][kk][0];
            ull bp[4];
            #pragma unroll
            for (int jp = 0; jp < 4; jp++) bp[jp] = brow[jp * 16 + tx];
            const ull* arow = (const ull*)&As[s][kk][0];
            ull aa[8];
            #pragma unroll
            for (int i = 0; i < 8; i++) aa[i] = arow[ty * 8 + i];
            #pragma unroll
            for (int i = 0; i < 8; i++)
                #pragma unroll
                for (int jp = 0; jp < 4; jp++)
                    FFMA2(acc2[i][jp], aa[i], bp[jp]);
        }
        __syncthreads();
    }

    // ---- epilogue ----
    float c4 = g_c[4];
    float part = 0.f;

    if (type == 0) {
        #pragma unroll
        for (int ii = 0; ii < 8; ii++) {
            int il = ty * 8 + ii;
            float si = sqI[il];
            int li = Li[il];
            float wcls = s_css[li];
            #pragma unroll
            for (int jp = 0; jp < 4; jp++) {
                float d0, d1;
                UNPACK2(d0, d1, acc2[ii][jp]);
                #pragma unroll
                for (int h = 0; h < 2; h++) {
                    int jl = tx * 8 + 2 * jp + h;
                    float dot = h ? d1 : d0;
                    float L2 = fmaxf(fmaf(-2.f, dot, si + sqJ[jl]), 0.f);
                    float e4 = ex2f(L2 * c4);
                    float e3 = e4 * e4, e2 = e3 * e3, e1 = e2 * e2, e0 = e1 * e1;
                    float ks = ((e0 + e1) + (e2 + e3)) + e4;
                    float w = (li == Lj[jl]) ? wcls : 0.f;
                    part = fmaf(w, ks, part);
                }
            }
        }
    } else if (type == 1) {
        const float4* Wt = (const float4*)(g_wtt + (size_t)triq * 16384);
        int base = (ty * 8) * 32 + tx * 2;
        float4 wa = Wt[base], wb = Wt[base + 1];
        #pragma unroll
        for (int ii = 0; ii < 8; ii++) {
            int il = ty * 8 + ii;
            float si = sqI[il];
            float wv[8] = { wa.x, wa.y, wa.z, wa.w, wb.x, wb.y, wb.z, wb.w };
            if (ii < 7) { wa = Wt[base + (ii + 1) * 32]; wb = Wt[base + (ii + 1) * 32 + 1]; }
            #pragma unroll
            for (int jp = 0; jp < 4; jp++) {
                float d0, d1;
                UNPACK2(d0, d1, acc2[ii][jp]);
                #pragma unroll
                for (int h = 0; h < 2; h++) {
                    int jj = 2 * jp + h;
                    int jl = tx * 8 + jj;
                    float dot = h ? d1 : d0;
                    float L2 = fmaxf(fmaf(-2.f, dot, si + sqJ[jl]), 0.f);
                    float e4 = ex2f(L2 * c4);
                    float e3 = e4 * e4, e2 = e3 * e3, e1 = e2 * e2, e0 = e1 * e1;
                    float ks = ((e0 + e1) + (e2 + e3)) + e4;
                    part = fmaf(wv[jj], ks, part);
                }
            }
        }
    } else {
        #pragma unroll
        for (int ii = 0; ii < 8; ii++) {
            int il = ty * 8 + ii;
            float si = sqI[il];
            int li = Li[il];
            float wc = s_cst[li];
            #pragma unroll
            for (int jp = 0; jp < 4; jp++) {
                float d0, d1;
                UNPACK2(d0, d1, acc2[ii][jp]);
                #pragma unroll
                for (int h = 0; h < 2; h++) {
                    int jl = tx * 8 + 2 * jp + h;
                    float dot = h ? d1 : d0;
                    float L2 = fmaxf(fmaf(-2.f, dot, si + sqJ[jl]), 0.f);
                    float e4 = ex2f(L2 * c4);
                    float e3 = e4 * e4, e2 = e3 * e3, e1 = e2 * e2, e0 = e1 * e1;
                    float ks = ((e0 + e1) + (e2 + e3)) + e4;
                    part = fmaf(wc * UjT[li][jl], ks, part);
                }
            }
        }
    }

    #pragma unroll
    for (int o = 16; o; o >>= 1) part += __shfl_xor_sync(0xffffffffu, part, o);
    if ((t & 31) == 0) {
        double f = (type < 2 && ti != tj) ? 2.0 : 1.0;
        atomicAdd(&g_acc[type], f * (double)part);
    }
}

// ---------------- output ----------------
__global__ void k_out(float* out) {
    out[0] = (float)(g_lamb * (g_acc[0] + g_acc[1] - 2.0 * g_acc[2]));
}

extern "C" void kernel_launch(void* const* d_in, const int* in_sizes, int n_in,
                              void* d_out, int out_size) {
    const float* src    = (const float*)d_in[0];
    const float* tgt    = (const float*)d_in[1];
    const int*   lbl    = (const int*)d_in[2];
    const float* logits = (const float*)d_in[3];
    const int*   iter   = (const int*)d_in[4];
    float* out = (float*)d_out;

    k_init<<<1, 512>>>();
    k_sq<<<(NTOT * 32) / 256, 256>>>(src, tgt);
    k_colsum<<<32, 512>>>(src, tgt);
    k_stats<<<16, 256>>>(lbl, logits);
    k_finalize<<<1, 512>>>(iter);
    k_u<<<16, 256>>>(logits);
    k_wtt<<<TRI, 256>>>();
    k_main<<<2 * TRI + NT * NT, 256>>>(src, tgt, lbl);
    k_out<<<1, 1>>>(out);
}

// round 9
// speedup vs baseline: 2.9707x; 2.9707x over previous
#include <cuda_runtime.h>
#include <cuda_bf16.h>
#include <math.h>
#include <stdint.h>

#define B_ROWS 4096
#define DIM    512
#define NCLS   31
#define NTOT   8192
#define NT     32        // 4096/128 tiles per side
#define TRI    528       // NT*(NT+1)/2

typedef unsigned long long ull;

// ---------------- device scratch ----------------
__device__ double g_sumsq;
__device__ double g_acc[3];
__device__ float  g_S[DIM];
__device__ float  g_sq[NTOT];
__device__ int    g_scount[NCLS];
__device__ int    g_tcount[NCLS];
__device__ float  g_tcolsum[NCLS];
__device__ float  g_css[NCLS];
__device__ float  g_cst[NCLS];
__device__ float  g_invts[NCLS];
__device__ __align__(16) float g_u[B_ROWS * 32];
__device__ float  g_c[5];
__device__ float  g_scale;
__device__ float  g_lamb;
// bf16 split of concat(source,target): 8192 x 512 each
__device__ __align__(16) __nv_bfloat16 g_hi[NTOT * DIM];
__device__ __align__(16) __nv_bfloat16 g_lo[NTOT * DIM];
// precomputed TT weights, upper-triangle tiles, [tri][128][128]
__device__ __align__(16) float g_wtt[TRI * 128 * 128];

// ---------------- init ----------------
__global__ void k_init() {
    int t = threadIdx.x;
    if (t == 0) g_sumsq = 0.0;
    if (t < 3) g_acc[t] = 0.0;
    if (t < NCLS) { g_scount[t] = 0; g_tcount[t] = 0; g_tcolsum[t] = 0.f; }
    if (t < DIM) g_S[t] = 0.f;
}

// ---------------- bf16 hi/lo split ----------------
__global__ void k_split(const float* __restrict__ src, const float* __restrict__ tgt) {
    int idx = blockIdx.x * blockDim.x + threadIdx.x;   // float4 index
    int e = idx * 4;
    int row = e >> 9;
    const float* base = (row < B_ROWS) ? src : (tgt - (size_t)B_ROWS * DIM);
    float4 v = *(const float4*)(base + e);
    __nv_bfloat16 h0 = __float2bfloat16(v.x);
    __nv_bfloat16 h1 = __float2bfloat16(v.y);
    __nv_bfloat16 h2 = __float2bfloat16(v.z);
    __nv_bfloat16 h3 = __float2bfloat16(v.w);
    __nv_bfloat16 l0 = __float2bfloat16(v.x - __bfloat162float(h0));
    __nv_bfloat16 l1 = __float2bfloat16(v.y - __bfloat162float(h1));
    __nv_bfloat16 l2 = __float2bfloat16(v.z - __bfloat162float(h2));
    __nv_bfloat16 l3 = __float2bfloat16(v.w - __bfloat162float(h3));
    __nv_bfloat162* H = (__nv_bfloat162*)g_hi;
    __nv_bfloat162* L = (__nv_bfloat162*)g_lo;
    H[idx * 2 + 0] = __nv_bfloat162(h0, h1);
    H[idx * 2 + 1] = __nv_bfloat162(h2, h3);
    L[idx * 2 + 0] = __nv_bfloat162(l0, l1);
    L[idx * 2 + 1] = __nv_bfloat162(l2, l3);
}

// ---------------- row squared norms ----------------
__global__ void k_sq(const float* __restrict__ src, const float* __restrict__ tgt) {
    int w = (blockIdx.x * blockDim.x + threadIdx.x) >> 5;
    int lane = threadIdx.x & 31;
    if (w >= NTOT) return;
    const float* row = (w < B_ROWS) ? (src + (size_t)w * DIM)
                                    : (tgt + (size_t)(w - B_ROWS) * DIM);
    float s = 0.f;
    for (int k = lane; k < DIM; k += 32) { float v = row[k]; s = fmaf(v, v, s); }
    #pragma unroll
    for (int o = 16; o; o >>= 1) s += __shfl_xor_sync(0xffffffffu, s, o);
    if (lane == 0) { g_sq[w] = s; atomicAdd(&g_sumsq, (double)s); }
}

// ---------------- column sums ----------------
__global__ void k_colsum(const float* __restrict__ src, const float* __restrict__ tgt) {
    int d = threadIdx.x;
    int b = blockIdx.x;
    float s = 0.f;
    int r0 = b * 128;
    for (int r = r0; r < r0 + 128; r++)
        s += src[(size_t)r * DIM + d] + tgt[(size_t)r * DIM + d];
    atomicAdd(&g_S[d], s);
}

// ---------------- class stats ----------------
__global__ void k_stats(const int* __restrict__ lbl, const float* __restrict__ logits) {
    int b = blockIdx.x;
    int t = threadIdx.x;
    int i = b * 256 + t;
    atomicAdd(&g_scount[lbl[i]], 1);
    const float* row = logits + (size_t)i * NCLS;
    float mv = row[0]; int mi = 0;
    #pragma unroll
    for (int c = 1; c < NCLS; c++) { float v = row[c]; if (v > mv) { mv = v; mi = c; } }
    atomicAdd(&g_tcount[mi], 1);
    if (t < NCLS) {
        float s = 0.f;
        for (int r = 0; r < 256; r++) s += logits[(size_t)(b * 256 + r) * NCLS + t];
        atomicAdd(&g_tcolsum[t], s);
    }
}

// ---------------- finalize ----------------
__global__ void k_finalize(const int* __restrict__ curr_iter) {
    __shared__ double sred[512];
    __shared__ float  sm[NCLS];
    __shared__ float  sscale;
    int t = threadIdx.x;
    double v = (double)g_S[t];
    sred[t] = v * v;
    __syncthreads();
    for (int o = 256; o; o >>= 1) { if (t < o) sred[t] += sred[t + o]; __syncthreads(); }
    if (t < NCLS) sm[t] = (g_scount[t] > 0 && g_tcount[t] > 0) ? 1.f : 0.f;
    __syncthreads();
    if (t == 0) {
        float cnt = 0.f;
        for (int c = 0; c < NCLS; c++) cnt += sm[c];
        sscale = (cnt > 0.f) ? 1.f / fmaxf(cnt, 1.f) : 0.f;
        g_scale = sscale;
    }
    __syncthreads();
    if (t < NCLS) {
        float m = sm[t];
        int sc = g_scount[t];
        float css = 0.f, cst = 0.f;
        if (sc > 0) { float fc = (float)sc; css = m * sscale / (fc * fc); cst = m * sscale / fc; }
        g_css[t] = css; g_cst[t] = cst;
        float ts = g_tcolsum[t]; if (ts == 0.f) ts = 100.f;
        g_invts[t] = m / ts;
    }
    if (t == 0) {
        double sumL2 = 2.0 * (double)NTOT * g_sumsq - 2.0 * sred[0];
        double bw = sumL2 / ((double)NTOT * (double)NTOT - (double)NTOT);
        bw = bw / 4.0;
        for (int i = 0; i < 5; i++)
            g_c[i] = (float)(-1.4426950408889634 / (bw * (double)(1 << i)));
        double p = (double)curr_iter[0] / 1000.0;
        g_lamb = (float)(2.0 / (1.0 + exp(-p)) - 1.0);
    }
}

// ---------------- masked normalized target logits ----------------
__global__ void k_u(const float* __restrict__ logits) {
    int i = blockIdx.x * blockDim.x + threadIdx.x;
    if (i >= B_ROWS) return;
    #pragma unroll
    for (int c = 0; c < NCLS; c++)
        g_u[i * 32 + c] = logits[(size_t)i * NCLS + c] * g_invts[c];
    g_u[i * 32 + 31] = 0.f;
}

// ---------------- precompute TT weight tiles: scale * U U^T ----------------
__global__ __launch_bounds__(256, 2)
void k_wtt() {
    __shared__ float Us[128][33];
    __shared__ float Ut[128][33];
    int bid = blockIdx.x;     // tri index
    int r = 0, b = bid;
    while (b >= NT - r) { b -= NT - r; r++; }
    int ti = r, tj = r + b;
    int gi0 = ti * 128, gj0 = tj * 128;
    int t = threadIdx.x;
    int tx = t & 15, ty = t >> 4;

    for (int idx = t; idx < 4096; idx += 256) {
        int row = idx >> 5, c = idx & 31;
        Us[row][c] = g_u[(size_t)(gi0 + row) * 32 + c];
        Ut[row][c] = g_u[(size_t)(gj0 + row) * 32 + c];
    }
    __syncthreads();

    float acc[8][8];
    #pragma unroll
    for (int i = 0; i < 8; i++)
        #pragma unroll
        for (int j = 0; j < 8; j++) acc[i][j] = 0.f;

    #pragma unroll 1
    for (int c = 0; c < NCLS; c++) {
        float a[8], bb[8];
        #pragma unroll
        for (int i = 0; i < 8; i++) a[i] = Us[ty * 8 + i][c];
        #pragma unroll
        for (int j = 0; j < 8; j++) bb[j] = Ut[tx * 8 + j][c];
        #pragma unroll
        for (int i = 0; i < 8; i++)
            #pragma unroll
            for (int j = 0; j < 8; j++)
                acc[i][j] = fmaf(a[i], bb[j], acc[i][j]);
    }

    float scale = g_scale;
    float* W = g_wtt + (size_t)bid * 16384;
    #pragma unroll
    for (int i = 0; i < 8; i++) {
        int il = ty * 8 + i;
        float4 v0 = make_float4(acc[i][0]*scale, acc[i][1]*scale, acc[i][2]*scale, acc[i][3]*scale);
        float4 v1 = make_float4(acc[i][4]*scale, acc[i][5]*scale, acc[i][6]*scale, acc[i][7]*scale);
        *(float4*)(W + il * 128 + tx * 8 + 0) = v0;
        *(float4*)(W + il * 128 + tx * 8 + 4) = v1;
    }
}

// ---------------- helpers ----------------
__device__ __forceinline__ float ex2f(float x) {
    float r; asm("ex2.approx.ftz.f32 %0, %1;" : "=f"(r) : "f"(x)); return r;
}
__device__ __forceinline__ uint32_t smem_u32(const void* p) {
    uint32_t a;
    asm("{ .reg .u64 t; cvta.to.shared.u64 t, %1; cvt.u32.u64 %0, t; }" : "=r"(a) : "l"(p));
    return a;
}
__device__ __forceinline__ void cp16(uint32_t dst, const void* src) {
    asm volatile("cp.async.cg.shared.global [%0], [%1], 16;" :: "r"(dst), "l"(src) : "memory");
}
#define CP_COMMIT() asm volatile("cp.async.commit_group;" ::: "memory")
#define CP_WAIT(n)  asm volatile("cp.async.wait_group %0;" :: "n"(n) : "memory")

#define LDSM4(r, addr) \
    asm volatile("ldmatrix.sync.aligned.m8n8.x4.shared.b16 {%0,%1,%2,%3}, [%4];" \
        : "=r"((r)[0]), "=r"((r)[1]), "=r"((r)[2]), "=r"((r)[3]) : "r"(addr))

#define MMA16816(d, a, b0_, b1_) \
    asm volatile("mma.sync.aligned.m16n8k16.row.col.f32.bf16.bf16.f32 " \
        "{%0,%1,%2,%3},{%4,%5,%6,%7},{%8,%9},{%0,%1,%2,%3};" \
        : "+f"((d)[0]), "+f"((d)[1]), "+f"((d)[2]), "+f"((d)[3]) \
        : "r"((a)[0]), "r"((a)[1]), "r"((a)[2]), "r"((a)[3]), "r"(b0_), "r"(b1_))

// XOR swizzle for 64B rows of 4x16B units (conflict-free for stores + both ldmatrix phases)
__device__ __forceinline__ uint32_t swz(int row, int j) {
    return (uint32_t)(row * 64 + ((j ^ ((row ^ (row >> 2)) & 3)) << 4));
}

// dynamic smem layout
#define SM_STAGES   0u          // 2 stages x 4 matrices x 8192B = 65536
#define SM_SQI      65536u
#define SM_SQJ      66048u
#define SM_LI       66560u
#define SM_LJ       67072u
#define SM_CSS      67584u
#define SM_CST      67712u
#define SM_UJT      67840u      // 32 x 128 floats = 16384
#define SM_TOTAL    84224u

// ---------------- main: bf16 mma.sync Gram + fused epilogue ----------------
__global__ __launch_bounds__(256, 2)
void k_main(const int* __restrict__ slabel) {
    extern __shared__ char smem[];
    uint32_t sb = smem_u32(smem);
    int t = threadIdx.x;
    int w = t >> 5, lane = t & 31;

    // tile decode
    int bid = blockIdx.x;
    int type, ti, tj, triq = 0;
    if (bid < TRI) { type = 0; }
    else if (bid < 2 * TRI) { type = 1; bid -= TRI; }
    else { type = 2; bid -= 2 * TRI; }
    if (type < 2) {
        int r = 0, b = bid;
        while (b >= NT - r) { b -= NT - r; r++; }
        ti = r; tj = r + b; triq = bid;
    } else { ti = bid >> 5; tj = bid & 31; }

    int gi0 = ti * 128, gj0 = tj * 128;
    int rowA0 = ((type == 1) ? B_ROWS : 0) + gi0;
    int rowB0 = ((type == 0) ? 0 : B_ROWS) + gj0;

    const char* bAh = (const char*)g_hi + (size_t)rowA0 * 1024;
    const char* bAl = (const char*)g_lo + (size_t)rowA0 * 1024;
    const char* bBh = (const char*)g_hi + (size_t)rowB0 * 1024;
    const char* bBl = (const char*)g_lo + (size_t)rowB0 * 1024;

    // ---- issue chunk 0 ----
    {
        uint32_t stb = sb + SM_STAGES;
        #pragma unroll
        for (int i = 0; i < 8; i++) {
            const int mat = i >> 1;
            int rem = (i & 1) * 256 + t;
            int row = rem >> 2, j = rem & 3;
            const char* srcB = (mat == 0) ? bAh : (mat == 1) ? bAl : (mat == 2) ? bBh : bBl;
            cp16(stb + mat * 8192 + swz(row, j), srcB + (size_t)row * 1024 + j * 16);
        }
        CP_COMMIT();
    }

    // ---- epilogue tables ----
    float* sqI = (float*)(smem + SM_SQI);
    float* sqJ = (float*)(smem + SM_SQJ);
    int*   Li  = (int*)(smem + SM_LI);
    int*   Lj  = (int*)(smem + SM_LJ);
    float* css = (float*)(smem + SM_CSS);
    float* cst = (float*)(smem + SM_CST);
    float* UjT = (float*)(smem + SM_UJT);   // [32][128]

    if (t < 128) {
        sqI[t] = g_sq[rowA0 + t];
        sqJ[t] = g_sq[rowB0 + t];
        Li[t] = (type != 1) ? slabel[gi0 + t] : 0;
        Lj[t] = (type == 0) ? slabel[gj0 + t] : 0;
    }
    if (t < NCLS) { css[t] = g_css[t]; cst[t] = g_cst[t]; }
    if (type == 2) {
        for (int idx = t; idx < 4096; idx += 256) {
            int c = idx >> 7, j = idx & 127;
            UjT[c * 128 + j] = g_u[(size_t)(gj0 + j) * 32 + c];
        }
    }

    // warp tiling: 4 x 2 warps, each 32(m) x 64(n)
    int m_base = (w & 3) * 32;
    int n_base = (w >> 2) * 64;
    int arow = (lane & 7) + 8 * ((lane >> 3) & 1);   // + m_base + 16*mi
    int brow = (lane & 7) + 8 * (lane >> 4);         // + n_base + 16*p
    int aj0 = (lane >> 4);          // unit low bit source for A
    int bj0 = ((lane >> 3) & 1);    // for B

    float acc[2][8][4];
    #pragma unroll
    for (int mi = 0; mi < 2; mi++)
        #pragma unroll
        for (int nt = 0; nt < 8; nt++)
            #pragma unroll
            for (int e = 0; e < 4; e++) acc[mi][nt][e] = 0.f;

    // ---- mainloop: 16 chunks of k=32, double buffered ----
    #pragma unroll 1
    for (int c = 0; c < 16; c++) {
        int s = c & 1;
        if (c < 15) {
            uint32_t stb = sb + SM_STAGES + (s ^ 1) * 32768;
            int koff = (c + 1) * 64;
            #pragma unroll
            for (int i = 0; i < 8; i++) {
                const int mat = i >> 1;
                int rem = (i & 1) * 256 + t;
                int row = rem >> 2, j = rem & 3;
                const char* srcB = (mat == 0) ? bAh : (mat == 1) ? bAl : (mat == 2) ? bBh : bBl;
                cp16(stb + mat * 8192 + swz(row, j), srcB + (size_t)row * 1024 + koff + j * 16);
            }
            CP_COMMIT();
            CP_WAIT(1);
        } else {
            CP_WAIT(0);
        }
        __syncthreads();

        uint32_t stb = sb + SM_STAGES + s * 32768;
        #pragma unroll
        for (int h = 0; h < 2; h++) {
            uint32_t Ah[2][4], Al[2][4];
            #pragma unroll
            for (int mi = 0; mi < 2; mi++) {
                int rA = m_base + mi * 16 + arow;
                uint32_t off = swz(rA, 2 * h + aj0);
                LDSM4(Ah[mi], stb + 0 * 8192 + off);
                LDSM4(Al[mi], stb + 1 * 8192 + off);
            }
            #pragma unroll
            for (int p = 0; p < 4; p++) {
                int rB = n_base + p * 16 + brow;
                uint32_t off = swz(rB, 2 * h + bj0);
                uint32_t Bh[4], Bl[4];
                LDSM4(Bh, stb + 2 * 8192 + off);
                LDSM4(Bl, stb + 3 * 8192 + off);
                #pragma unroll
                for (int mi = 0; mi < 2; mi++) {
                    MMA16816(acc[mi][2 * p + 0], Ah[mi], Bh[0], Bh[1]);
                    MMA16816(acc[mi][2 * p + 1], Ah[mi], Bh[2], Bh[3]);
                    MMA16816(acc[mi][2 * p + 0], Ah[mi], Bl[0], Bl[1]);
                    MMA16816(acc[mi][2 * p + 1], Ah[mi], Bl[2], Bl[3]);
                    MMA16816(acc[mi][2 * p + 0], Al[mi], Bh[0], Bh[1]);
                    MMA16816(acc[mi][2 * p + 1], Al[mi], Bh[2], Bh[3]);
                }
            }
        }
        __syncthreads();
    }

    // ---- epilogue ----
    float c4 = g_c[4];
    float part = 0.f;
    int r0 = m_base + (lane >> 2);
    int c0 = n_base + 2 * (lane & 3);
    const float* Wt = (type == 1) ? (g_wtt + (size_t)triq * 16384) : g_wtt;

    #pragma unroll
    for (int mi = 0; mi < 2; mi++) {
        #pragma unroll
        for (int half = 0; half < 2; half++) {
            int r = r0 + mi * 16 + half * 8;
            float si = sqI[r];
            int li = Li[r];
            float wss = css[li];
            float wst = cst[li];
            const float* ujrow = UjT + li * 128;
            #pragma unroll
            for (int nt = 0; nt < 8; nt++) {
                int cc = c0 + nt * 8;
                float d0 = acc[mi][nt][half * 2 + 0];
                float d1 = acc[mi][nt][half * 2 + 1];
                float w0, w1;
                if (type == 0) {
                    w0 = (li == Lj[cc]) ? wss : 0.f;
                    w1 = (li == Lj[cc + 1]) ? wss : 0.f;
                } else if (type == 1) {
                    float2 wv = *(const float2*)(Wt + r * 128 + cc);
                    w0 = wv.x; w1 = wv.y;
                } else {
                    w0 = wst * ujrow[cc];
                    w1 = wst * ujrow[cc + 1];
                }
                float L2a = fmaxf(fmaf(-2.f, d0, si + sqJ[cc]), 0.f);
                float L2b = fmaxf(fmaf(-2.f, d1, si + sqJ[cc + 1]), 0.f);
                float ea4 = ex2f(L2a * c4);
                float eb4 = ex2f(L2b * c4);
                float ea3 = ea4 * ea4, ea2 = ea3 * ea3, ea1 = ea2 * ea2, ea0 = ea1 * ea1;
                float eb3 = eb4 * eb4, eb2 = eb3 * eb3, eb1 = eb2 * eb2, eb0 = eb1 * eb1;
                float ksa = ((ea0 + ea1) + (ea2 + ea3)) + ea4;
                float ksb = ((eb0 + eb1) + (eb2 + eb3)) + eb4;
                part = fmaf(w0, ksa, part);
                part = fmaf(w1, ksb, part);
            }
        }
    }

    #pragma unroll
    for (int o = 16; o; o >>= 1) part += __shfl_xor_sync(0xffffffffu, part, o);
    if (lane == 0) {
        double f = (type < 2 && ti != tj) ? 2.0 : 1.0;
        atomicAdd(&g_acc[type], f * (double)part);
    }
}

// ---------------- output ----------------
__global__ void k_out(float* out) {
    out[0] = (float)(g_lamb * (g_acc[0] + g_acc[1] - 2.0 * g_acc[2]));
}

extern "C" void kernel_launch(void* const* d_in, const int* in_sizes, int n_in,
                              void* d_out, int out_size) {
    const float* src    = (const float*)d_in[0];
    const float* tgt    = (const float*)d_in[1];
    const int*   lbl    = (const int*)d_in[2];
    const float* logits = (const float*)d_in[3];
    const int*   iter   = (const int*)d_in[4];
    float* out = (float*)d_out;

    cudaFuncSetAttribute(k_main, cudaFuncAttributeMaxDynamicSharedMemorySize, SM_TOTAL);

    k_init<<<1, 512>>>();
    k_split<<<(NTOT * DIM / 4) / 256, 256>>>(src, tgt);
    k_sq<<<(NTOT * 32) / 256, 256>>>(src, tgt);
    k_colsum<<<32, 512>>>(src, tgt);
    k_stats<<<16, 256>>>(lbl, logits);
    k_finalize<<<1, 512>>>(iter);
    k_u<<<16, 256>>>(logits);
    k_wtt<<<TRI, 256>>>();
    k_main<<<2 * TRI + NT * NT, 256, SM_TOTAL>>>(lbl);
    k_out<<<1, 1>>>(out);
}

// round 10
// speedup vs baseline: 3.1196x; 1.0501x over previous
#include <cuda_runtime.h>
#include <cuda_bf16.h>
#include <math.h>
#include <stdint.h>

#define B_ROWS 4096
#define DIM    512
#define NCLS   31
#define NTOT   8192
#define NT     32        // 4096/128 tiles per side
#define TRI    528       // NT*(NT+1)/2

typedef unsigned long long ull;

// ---------------- device scratch ----------------
__device__ double g_acc[3];
__device__ float  g_S[DIM];
__device__ float  g_sq[NTOT];
__device__ int    g_scount[NCLS];
__device__ int    g_tcount[NCLS];
__device__ float  g_tcolsum[NCLS];
__device__ float  g_css[NCLS];
__device__ float  g_cst[NCLS];
__device__ float  g_invts[NCLS];
__device__ __align__(16) float g_u[B_ROWS * 32];
__device__ float  g_c[5];
__device__ float  g_scale;
__device__ float  g_lamb;
// bf16 split of concat(source,target): 8192 x 512 each
__device__ __align__(16) __nv_bfloat16 g_hi[NTOT * DIM];
__device__ __align__(16) __nv_bfloat16 g_lo[NTOT * DIM];
// precomputed TT weights in bf16, upper-triangle tiles, [tri][128][128]
__device__ __align__(16) __nv_bfloat16 g_wttb[TRI * 128 * 128];

// ---------------- init ----------------
__global__ void k_init() {
    int t = threadIdx.x;
    if (t < 3) g_acc[t] = 0.0;
    if (t < NCLS) { g_scount[t] = 0; g_tcount[t] = 0; g_tcolsum[t] = 0.f; }
    if (t < DIM) g_S[t] = 0.f;
    for (int i = t; i < NTOT; i += 512) g_sq[i] = 0.f;
}

// ---------------- bf16 hi/lo split + fused row sq-norms ----------------
__global__ void k_split(const float* __restrict__ src, const float* __restrict__ tgt) {
    int idx = blockIdx.x * blockDim.x + threadIdx.x;   // float4 index
    int lane = threadIdx.x & 31;
    int e = idx * 4;
    int row = e >> 9;     // one warp covers 128 consecutive floats -> single row
    const float* base = (row < B_ROWS) ? src : (tgt - (size_t)B_ROWS * DIM);
    float4 v = *(const float4*)(base + e);
    __nv_bfloat16 h0 = __float2bfloat16(v.x);
    __nv_bfloat16 h1 = __float2bfloat16(v.y);
    __nv_bfloat16 h2 = __float2bfloat16(v.z);
    __nv_bfloat16 h3 = __float2bfloat16(v.w);
    __nv_bfloat16 l0 = __float2bfloat16(v.x - __bfloat162float(h0));
    __nv_bfloat16 l1 = __float2bfloat16(v.y - __bfloat162float(h1));
    __nv_bfloat16 l2 = __float2bfloat16(v.z - __bfloat162float(h2));
    __nv_bfloat16 l3 = __float2bfloat16(v.w - __bfloat162float(h3));
    __nv_bfloat162* H = (__nv_bfloat162*)g_hi;
    __nv_bfloat162* L = (__nv_bfloat162*)g_lo;
    H[idx * 2 + 0] = __nv_bfloat162(h0, h1);
    H[idx * 2 + 1] = __nv_bfloat162(h2, h3);
    L[idx * 2 + 0] = __nv_bfloat162(l0, l1);
    L[idx * 2 + 1] = __nv_bfloat162(l2, l3);
    // fused row squared-norm partial (quarter-row per warp)
    float s = fmaf(v.x, v.x, fmaf(v.y, v.y, fmaf(v.z, v.z, v.w * v.w)));
    #pragma unroll
    for (int o = 16; o; o >>= 1) s += __shfl_xor_sync(0xffffffffu, s, o);
    if (lane == 0) atomicAdd(&g_sq[row], s);
}

// ---------------- column sums (widened grid: BW-bound) ----------------
__global__ void k_colsum(const float* __restrict__ src, const float* __restrict__ tgt) {
    int d = threadIdx.x;   // 512 threads
    int b = blockIdx.x;    // 256 blocks, 16 rows each per array
    float s = 0.f;
    int r0 = b * 16;
    for (int r = r0; r < r0 + 16; r++)
        s += src[(size_t)r * DIM + d] + tgt[(size_t)r * DIM + d];
    atomicAdd(&g_S[d], s);
}

// ---------------- class stats ----------------
__global__ void k_stats(const int* __restrict__ lbl, const float* __restrict__ logits) {
    int b = blockIdx.x;
    int t = threadIdx.x;
    int i = b * 256 + t;
    atomicAdd(&g_scount[lbl[i]], 1);
    const float* row = logits + (size_t)i * NCLS;
    float mv = row[0]; int mi = 0;
    #pragma unroll
    for (int c = 1; c < NCLS; c++) { float v = row[c]; if (v > mv) { mv = v; mi = c; } }
    atomicAdd(&g_tcount[mi], 1);
    if (t < NCLS) {
        float s = 0.f;
        for (int r = 0; r < 256; r++) s += logits[(size_t)(b * 256 + r) * NCLS + t];
        atomicAdd(&g_tcolsum[t], s);
    }
}

// ---------------- finalize ----------------
__global__ void k_finalize(const int* __restrict__ curr_iter) {
    __shared__ double sred[512];
    __shared__ float  sm[NCLS];
    __shared__ float  sscale;
    int t = threadIdx.x;  // 512 threads
    // combined reduction: sumL2 = sum_t [ 2*NTOT*sq_part(t) - 2*S[t]^2 ]
    double sq_part = 0.0;
    for (int i = t; i < NTOT; i += 512) sq_part += (double)g_sq[i];
    double Sv = (double)g_S[t];
    sred[t] = 2.0 * (double)NTOT * sq_part - 2.0 * Sv * Sv;
    __syncthreads();
    for (int o = 256; o; o >>= 1) { if (t < o) sred[t] += sred[t + o]; __syncthreads(); }
    if (t < NCLS) sm[t] = (g_scount[t] > 0 && g_tcount[t] > 0) ? 1.f : 0.f;
    __syncthreads();
    if (t == 0) {
        float cnt = 0.f;
        for (int c = 0; c < NCLS; c++) cnt += sm[c];
        sscale = (cnt > 0.f) ? 1.f / fmaxf(cnt, 1.f) : 0.f;
        g_scale = sscale;
    }
    __syncthreads();
    if (t < NCLS) {
        float m = sm[t];
        int sc = g_scount[t];
        float css = 0.f, cst = 0.f;
        if (sc > 0) { float fc = (float)sc; css = m * sscale / (fc * fc); cst = m * sscale / fc; }
        g_css[t] = css; g_cst[t] = cst;
        float ts = g_tcolsum[t]; if (ts == 0.f) ts = 100.f;
        g_invts[t] = m / ts;
    }
    if (t == 0) {
        double sumL2 = sred[0];
        double bw = sumL2 / ((double)NTOT * (double)NTOT - (double)NTOT);
        bw = bw / 4.0;
        for (int i = 0; i < 5; i++)
            g_c[i] = (float)(-1.4426950408889634 / (bw * (double)(1 << i)));
        double p = (double)curr_iter[0] / 1000.0;
        g_lamb = (float)(2.0 / (1.0 + exp(-p)) - 1.0);
    }
}

// ---------------- masked normalized target logits ----------------
__global__ void k_u(const float* __restrict__ logits) {
    int i = blockIdx.x * blockDim.x + threadIdx.x;
    if (i >= B_ROWS) return;
    #pragma unroll
    for (int c = 0; c < NCLS; c++)
        g_u[i * 32 + c] = logits[(size_t)i * NCLS + c] * g_invts[c];
    g_u[i * 32 + 31] = 0.f;
}

// ---------------- precompute TT weight tiles (bf16): scale * U U^T ---------
__global__ __launch_bounds__(256, 2)
void k_wtt() {
    __shared__ float Us[128][33];
    __shared__ float Ut[128][33];
    int bid = blockIdx.x;     // tri index
    int r = 0, b = bid;
    while (b >= NT - r) { b -= NT - r; r++; }
    int ti = r, tj = r + b;
    int gi0 = ti * 128, gj0 = tj * 128;
    int t = threadIdx.x;
    int tx = t & 15, ty = t >> 4;

    for (int idx = t; idx < 4096; idx += 256) {
        int row = idx >> 5, c = idx & 31;
        Us[row][c] = g_u[(size_t)(gi0 + row) * 32 + c];
        Ut[row][c] = g_u[(size_t)(gj0 + row) * 32 + c];
    }
    __syncthreads();

    float acc[8][8];
    #pragma unroll
    for (int i = 0; i < 8; i++)
        #pragma unroll
        for (int j = 0; j < 8; j++) acc[i][j] = 0.f;

    #pragma unroll 1
    for (int c = 0; c < NCLS; c++) {
        float a[8], bb[8];
        #pragma unroll
        for (int i = 0; i < 8; i++) a[i] = Us[ty * 8 + i][c];
        #pragma unroll
        for (int j = 0; j < 8; j++) bb[j] = Ut[tx * 8 + j][c];
        #pragma unroll
        for (int i = 0; i < 8; i++)
            #pragma unroll
            for (int j = 0; j < 8; j++)
                acc[i][j] = fmaf(a[i], bb[j], acc[i][j]);
    }

    float scale = g_scale;
    __nv_bfloat16* W = g_wttb + (size_t)bid * 16384;
    #pragma unroll
    for (int i = 0; i < 8; i++) {
        int il = ty * 8 + i;
        __nv_bfloat162 p0 = __float22bfloat162_rn(make_float2(acc[i][0]*scale, acc[i][1]*scale));
        __nv_bfloat162 p1 = __float22bfloat162_rn(make_float2(acc[i][2]*scale, acc[i][3]*scale));
        __nv_bfloat162 p2 = __float22bfloat162_rn(make_float2(acc[i][4]*scale, acc[i][5]*scale));
        __nv_bfloat162 p3 = __float22bfloat162_rn(make_float2(acc[i][6]*scale, acc[i][7]*scale));
        uint4 pk;
        pk.x = *(uint32_t*)&p0; pk.y = *(uint32_t*)&p1;
        pk.z = *(uint32_t*)&p2; pk.w = *(uint32_t*)&p3;
        *(uint4*)(W + il * 128 + tx * 8) = pk;
    }
}

// ---------------- helpers ----------------
__device__ __forceinline__ float ex2f(float x) {
    float r; asm("ex2.approx.ftz.f32 %0, %1;" : "=f"(r) : "f"(x)); return r;
}
__device__ __forceinline__ uint32_t smem_u32(const void* p) {
    uint32_t a;
    asm("{ .reg .u64 t; cvta.to.shared.u64 t, %1; cvt.u32.u64 %0, t; }" : "=r"(a) : "l"(p));
    return a;
}
__device__ __forceinline__ void cp16(uint32_t dst, const void* src) {
    asm volatile("cp.async.cg.shared.global [%0], [%1], 16;" :: "r"(dst), "l"(src) : "memory");
}
#define CP_COMMIT() asm volatile("cp.async.commit_group;" ::: "memory")
#define CP_WAIT(n)  asm volatile("cp.async.wait_group %0;" :: "n"(n) : "memory")

#define LDSM4(r, addr) \
    asm volatile("ldmatrix.sync.aligned.m8n8.x4.shared.b16 {%0,%1,%2,%3}, [%4];" \
        : "=r"((r)[0]), "=r"((r)[1]), "=r"((r)[2]), "=r"((r)[3]) : "r"(addr))

#define MMA16816(d, a, b0_, b1_) \
    asm volatile("mma.sync.aligned.m16n8k16.row.col.f32.bf16.bf16.f32 " \
        "{%0,%1,%2,%3},{%4,%5,%6,%7},{%8,%9},{%0,%1,%2,%3};" \
        : "+f"((d)[0]), "+f"((d)[1]), "+f"((d)[2]), "+f"((d)[3]) \
        : "r"((a)[0]), "r"((a)[1]), "r"((a)[2]), "r"((a)[3]), "r"(b0_), "r"(b1_))

// XOR swizzle for 64B rows of 4x16B units
__device__ __forceinline__ uint32_t swz(int row, int j) {
    return (uint32_t)(row * 64 + ((j ^ ((row ^ (row >> 2)) & 3)) << 4));
}

// dynamic smem layout
#define SM_STAGES   0u          // 2 stages x 4 matrices x 8192B = 65536
#define SM_SQI      65536u
#define SM_SQJ      66048u
#define SM_LI       66560u
#define SM_LJ       67072u
#define SM_CSS      67584u
#define SM_CST      67712u
#define SM_UJT      67840u      // 32 x 128 floats = 16384
#define SM_TOTAL    84224u

// ---------------- main: bf16 mma.sync Gram + fused epilogue ----------------
__global__ __launch_bounds__(256, 2)
void k_main(const int* __restrict__ slabel) {
    extern __shared__ char smem[];
    uint32_t sb = smem_u32(smem);
    int t = threadIdx.x;
    int w = t >> 5, lane = t & 31;

    // tile decode
    int bid = blockIdx.x;
    int type, ti, tj, triq = 0;
    if (bid < TRI) { type = 0; }
    else if (bid < 2 * TRI) { type = 1; bid -= TRI; }
    else { type = 2; bid -= 2 * TRI; }
    if (type < 2) {
        int r = 0, b = bid;
        while (b >= NT - r) { b -= NT - r; r++; }
        ti = r; tj = r + b; triq = bid;
    } else { ti = bid >> 5; tj = bid & 31; }

    int gi0 = ti * 128, gj0 = tj * 128;
    int rowA0 = ((type == 1) ? B_ROWS : 0) + gi0;
    int rowB0 = ((type == 0) ? 0 : B_ROWS) + gj0;

    const char* bAh = (const char*)g_hi + (size_t)rowA0 * 1024;
    const char* bAl = (const char*)g_lo + (size_t)rowA0 * 1024;
    const char* bBh = (const char*)g_hi + (size_t)rowB0 * 1024;
    const char* bBl = (const char*)g_lo + (size_t)rowB0 * 1024;

    // ---- issue chunk 0 ----
    {
        uint32_t stb = sb + SM_STAGES;
        #pragma unroll
        for (int i = 0; i < 8; i++) {
            const int mat = i >> 1;
            int rem = (i & 1) * 256 + t;
            int row = rem >> 2, j = rem & 3;
            const char* srcB = (mat == 0) ? bAh : (mat == 1) ? bAl : (mat == 2) ? bBh : bBl;
            cp16(stb + mat * 8192 + swz(row, j), srcB + (size_t)row * 1024 + j * 16);
        }
        CP_COMMIT();
    }

    // ---- epilogue tables ----
    float* sqI = (float*)(smem + SM_SQI);
    float* sqJ = (float*)(smem + SM_SQJ);
    int*   Li  = (int*)(smem + SM_LI);
    int*   Lj  = (int*)(smem + SM_LJ);
    float* css = (float*)(smem + SM_CSS);
    float* cst = (float*)(smem + SM_CST);
    float* UjT = (float*)(smem + SM_UJT);   // [32][128]

    if (t < 128) {
        sqI[t] = g_sq[rowA0 + t];
        sqJ[t] = g_sq[rowB0 + t];
        Li[t] = (type != 1) ? slabel[gi0 + t] : 0;
        Lj[t] = (type == 0) ? slabel[gj0 + t] : 0;
    }
    if (t < NCLS) { css[t] = g_css[t]; cst[t] = g_cst[t]; }
    if (type == 2) {
        for (int idx = t; idx < 4096; idx += 256) {
            int c = idx >> 7, j = idx & 127;
            UjT[c * 128 + j] = g_u[(size_t)(gj0 + j) * 32 + c];
        }
    }

    // warp tiling: 4 x 2 warps, each 32(m) x 64(n)
    int m_base = (w & 3) * 32;
    int n_base = (w >> 2) * 64;
    int arow = (lane & 7) + 8 * ((lane >> 3) & 1);
    int brow = (lane & 7) + 8 * (lane >> 4);
    int aj0 = (lane >> 4);
    int bj0 = ((lane >> 3) & 1);

    float acc[2][8][4];
    #pragma unroll
    for (int mi = 0; mi < 2; mi++)
        #pragma unroll
        for (int nt = 0; nt < 8; nt++)
            #pragma unroll
            for (int e = 0; e < 4; e++) acc[mi][nt][e] = 0.f;

    // ---- mainloop: 16 chunks of k=32, double buffered ----
    #pragma unroll 1
    for (int c = 0; c < 16; c++) {
        int s = c & 1;
        if (c < 15) {
            uint32_t stb = sb + SM_STAGES + (s ^ 1) * 32768;
            int koff = (c + 1) * 64;
            #pragma unroll
            for (int i = 0; i < 8; i++) {
                const int mat = i >> 1;
                int rem = (i & 1) * 256 + t;
                int row = rem >> 2, j = rem & 3;
                const char* srcB = (mat == 0) ? bAh : (mat == 1) ? bAl : (mat == 2) ? bBh : bBl;
                cp16(stb + mat * 8192 + swz(row, j), srcB + (size_t)row * 1024 + koff + j * 16);
            }
            CP_COMMIT();
            CP_WAIT(1);
        } else {
            CP_WAIT(0);
        }
        __syncthreads();

        uint32_t stb = sb + SM_STAGES + s * 32768;
        #pragma unroll
        for (int h = 0; h < 2; h++) {
            uint32_t Ah[2][4], Al[2][4];
            #pragma unroll
            for (int mi = 0; mi < 2; mi++) {
                int rA = m_base + mi * 16 + arow;
                uint32_t off = swz(rA, 2 * h + aj0);
                LDSM4(Ah[mi], stb + 0 * 8192 + off);
                LDSM4(Al[mi], stb + 1 * 8192 + off);
            }
            #pragma unroll
            for (int p = 0; p < 4; p++) {
                int rB = n_base + p * 16 + brow;
                uint32_t off = swz(rB, 2 * h + bj0);
                uint32_t Bh[4], Bl[4];
                LDSM4(Bh, stb + 2 * 8192 + off);
                LDSM4(Bl, stb + 3 * 8192 + off);
                #pragma unroll
                for (int mi = 0; mi < 2; mi++) {
                    MMA16816(acc[mi][2 * p + 0], Ah[mi], Bh[0], Bh[1]);
                    MMA16816(acc[mi][2 * p + 1], Ah[mi], Bh[2], Bh[3]);
                    MMA16816(acc[mi][2 * p + 0], Ah[mi], Bl[0], Bl[1]);
                    MMA16816(acc[mi][2 * p + 1], Ah[mi], Bl[2], Bl[3]);
                    MMA16816(acc[mi][2 * p + 0], Al[mi], Bh[0], Bh[1]);
                    MMA16816(acc[mi][2 * p + 1], Al[mi], Bh[2], Bh[3]);
                }
            }
        }
        __syncthreads();
    }

    // ---- epilogue ----
    float c4 = g_c[4];
    float part = 0.f;
    int r0 = m_base + (lane >> 2);
    int c0 = n_base + 2 * (lane & 3);
    const __nv_bfloat162* Wt = (const __nv_bfloat162*)(g_wttb + (size_t)triq * 16384);

    #pragma unroll
    for (int mi = 0; mi < 2; mi++) {
        #pragma unroll
        for (int half = 0; half < 2; half++) {
            int r = r0 + mi * 16 + half * 8;
            float si = sqI[r];
            int li = Li[r];
            float wss = css[li];
            float wst = cst[li];
            const float* ujrow = UjT + li * 128;
            #pragma unroll
            for (int nt = 0; nt < 8; nt++) {
                int cc = c0 + nt * 8;
                float d0 = acc[mi][nt][half * 2 + 0];
                float d1 = acc[mi][nt][half * 2 + 1];
                float w0, w1;
                if (type == 0) {
                    w0 = (li == Lj[cc]) ? wss : 0.f;
                    w1 = (li == Lj[cc + 1]) ? wss : 0.f;
                } else if (type == 1) {
                    float2 wv = __bfloat1622float2(Wt[(r * 128 + cc) >> 1]);
                    w0 = wv.x; w1 = wv.y;
                } else {
                    w0 = wst * ujrow[cc];
                    w1 = wst * ujrow[cc + 1];
                }
                float L2a = fmaxf(fmaf(-2.f, d0, si + sqJ[cc]), 0.f);
                float L2b = fmaxf(fmaf(-2.f, d1, si + sqJ[cc + 1]), 0.f);
                float ea4 = ex2f(L2a * c4);
                float eb4 = ex2f(L2b * c4);
                float ea3 = ea4 * ea4, ea2 = ea3 * ea3, ea1 = ea2 * ea2, ea0 = ea1 * ea1;
                float eb3 = eb4 * eb4, eb2 = eb3 * eb3, eb1 = eb2 * eb2, eb0 = eb1 * eb1;
                float ksa = ((ea0 + ea1) + (ea2 + ea3)) + ea4;
                float ksb = ((eb0 + eb1) + (eb2 + eb3)) + eb4;
                part = fmaf(w0, ksa, part);
                part = fmaf(w1, ksb, part);
            }
        }
    }

    #pragma unroll
    for (int o = 16; o; o >>= 1) part += __shfl_xor_sync(0xffffffffu, part, o);
    if (lane == 0) {
        double f = (type < 2 && ti != tj) ? 2.0 : 1.0;
        atomicAdd(&g_acc[type], f * (double)part);
    }
}

// ---------------- output ----------------
__global__ void k_out(float* out) {
    out[0] = (float)(g_lamb * (g_acc[0] + g_acc[1] - 2.0 * g_acc[2]));
}

extern "C" void kernel_launch(void* const* d_in, const int* in_sizes, int n_in,
                              void* d_out, int out_size) {
    const float* src    = (const float*)d_in[0];
    const float* tgt    = (const float*)d_in[1];
    const int*   lbl    = (const int*)d_in[2];
    const float* logits = (const float*)d_in[3];
    const int*   iter   = (const int*)d_in[4];
    float* out = (float*)d_out;

    cudaFuncSetAttribute(k_main, cudaFuncAttributeMaxDynamicSharedMemorySize, SM_TOTAL);

    k_init<<<1, 512>>>();
    k_split<<<(NTOT * DIM / 4) / 256, 256>>>(src, tgt);
    k_colsum<<<256, 512>>>(src, tgt);
    k_stats<<<16, 256>>>(lbl, logits);
    k_finalize<<<1, 512>>>(iter);
    k_u<<<16, 256>>>(logits);
    k_wtt<<<TRI, 256>>>();
    k_main<<<2 * TRI + NT * NT, 256, SM_TOTAL>>>(lbl);
    k_out<<<1, 1>>>(out);
}

// round 11
// speedup vs baseline: 3.1233x; 1.0012x over previous
#include <cuda_runtime.h>
#include <cuda_bf16.h>
#include <math.h>
#include <stdint.h>

#define B_ROWS 4096
#define DIM    512
#define NCLS   31
#define NTOT   8192
#define NT     32        // 4096/128 tiles per side
#define TRI    528       // NT*(NT+1)/2

typedef unsigned long long ull;

// ---------------- device scratch ----------------
__device__ double g_acc[3];
__device__ float  g_S[DIM];
__device__ float  g_sq[NTOT];
__device__ int    g_scount[NCLS];
__device__ int    g_tcount[NCLS];
__device__ float  g_tcolsum[NCLS];
__device__ float  g_css[NCLS];
__device__ float  g_cst[NCLS];
__device__ float  g_invts[NCLS];
__device__ __align__(16) float g_u[B_ROWS * 32];
__device__ float  g_c[5];
__device__ float  g_scale;
__device__ float  g_lamb;
// bf16 split of concat(source,target): 8192 x 512 each
__device__ __align__(16) __nv_bfloat16 g_hi[NTOT * DIM];
__device__ __align__(16) __nv_bfloat16 g_lo[NTOT * DIM];
// precomputed TT weights (fp32 for accuracy), upper-triangle tiles
__device__ __align__(16) float g_wtt[TRI * 128 * 128];

// ---------------- bf16 hi/lo split + fused row sq-norms + init ----------------
__global__ void k_split(const float* __restrict__ src, const float* __restrict__ tgt) {
    __shared__ float part[8];
    int t = threadIdx.x;
    int idx = blockIdx.x * blockDim.x + t;   // float4 index
    int lane = t & 31, w = t >> 5;
    int e = idx * 4;
    int row = e >> 9;     // block covers 1024 floats = rows 2b, 2b+1
    const float* base = (row < B_ROWS) ? src : (tgt - (size_t)B_ROWS * DIM);
    float4 v = *(const float4*)(base + e);
    __nv_bfloat16 h0 = __float2bfloat16(v.x);
    __nv_bfloat16 h1 = __float2bfloat16(v.y);
    __nv_bfloat16 h2 = __float2bfloat16(v.z);
    __nv_bfloat16 h3 = __float2bfloat16(v.w);
    __nv_bfloat16 l0 = __float2bfloat16(v.x - __bfloat162float(h0));
    __nv_bfloat16 l1 = __float2bfloat16(v.y - __bfloat162float(h1));
    __nv_bfloat16 l2 = __float2bfloat16(v.z - __bfloat162float(h2));
    __nv_bfloat16 l3 = __float2bfloat16(v.w - __bfloat162float(h3));
    __nv_bfloat162* H = (__nv_bfloat162*)g_hi;
    __nv_bfloat162* L = (__nv_bfloat162*)g_lo;
    H[idx * 2 + 0] = __nv_bfloat162(h0, h1);
    H[idx * 2 + 1] = __nv_bfloat162(h2, h3);
    L[idx * 2 + 0] = __nv_bfloat162(l0, l1);
    L[idx * 2 + 1] = __nv_bfloat162(l2, l3);
    // row squared-norm: warps 0-3 -> row 2b, warps 4-7 -> row 2b+1 (no atomics)
    float s = fmaf(v.x, v.x, fmaf(v.y, v.y, fmaf(v.z, v.z, v.w * v.w)));
    #pragma unroll
    for (int o = 16; o; o >>= 1) s += __shfl_xor_sync(0xffffffffu, s, o);
    if (lane == 0) part[w] = s;
    __syncthreads();
    if (t < 2) {
        float r = part[t * 4] + part[t * 4 + 1] + part[t * 4 + 2] + part[t * 4 + 3];
        g_sq[blockIdx.x * 2 + t] = r;
    }
    // fold init (kernel boundary orders this before the atomics users)
    if (blockIdx.x == 0) {
        if (t < 3) g_acc[t] = 0.0;
        if (t < NCLS) { g_scount[t] = 0; g_tcount[t] = 0; g_tcolsum[t] = 0.f; }
        g_S[t] = 0.f; g_S[t + 256] = 0.f;
    }
}

// ---------------- column sums (wide grid: BW-bound) ----------------
__global__ void k_colsum(const float* __restrict__ src, const float* __restrict__ tgt) {
    int d = threadIdx.x;   // 512 threads
    int b = blockIdx.x;    // 256 blocks, 16 rows each per array
    float s = 0.f;
    int r0 = b * 16;
    for (int r = r0; r < r0 + 16; r++)
        s += src[(size_t)r * DIM + d] + tgt[(size_t)r * DIM + d];
    atomicAdd(&g_S[d], s);
}

// ---------------- class stats (widened: 32 x 128) ----------------
__global__ void k_stats(const int* __restrict__ lbl, const float* __restrict__ logits) {
    int b = blockIdx.x;
    int t = threadIdx.x;
    int i = b * 128 + t;
    atomicAdd(&g_scount[lbl[i]], 1);
    const float* row = logits + (size_t)i * NCLS;
    float mv = row[0]; int mi = 0;
    #pragma unroll
    for (int c = 1; c < NCLS; c++) { float v = row[c]; if (v > mv) { mv = v; mi = c; } }
    atomicAdd(&g_tcount[mi], 1);
    if (t < NCLS) {
        float s = 0.f;
        for (int r = 0; r < 128; r++) s += logits[(size_t)(b * 128 + r) * NCLS + t];
        atomicAdd(&g_tcolsum[t], s);
    }
}

// ---------------- finalize ----------------
__global__ void k_finalize(const int* __restrict__ curr_iter) {
    __shared__ double sred[512];
    __shared__ float  sm[NCLS];
    __shared__ float  sscale;
    int t = threadIdx.x;  // 512 threads
    double sq_part = 0.0;
    for (int i = t; i < NTOT; i += 512) sq_part += (double)g_sq[i];
    double Sv = (double)g_S[t];
    sred[t] = 2.0 * (double)NTOT * sq_part - 2.0 * Sv * Sv;
    __syncthreads();
    for (int o = 256; o; o >>= 1) { if (t < o) sred[t] += sred[t + o]; __syncthreads(); }
    if (t < NCLS) sm[t] = (g_scount[t] > 0 && g_tcount[t] > 0) ? 1.f : 0.f;
    __syncthreads();
    if (t == 0) {
        float cnt = 0.f;
        for (int c = 0; c < NCLS; c++) cnt += sm[c];
        sscale = (cnt > 0.f) ? 1.f / fmaxf(cnt, 1.f) : 0.f;
        g_scale = sscale;
    }
    __syncthreads();
    if (t < NCLS) {
        float m = sm[t];
        int sc = g_scount[t];
        float css = 0.f, cst = 0.f;
        if (sc > 0) { float fc = (float)sc; css = m * sscale / (fc * fc); cst = m * sscale / fc; }
        g_css[t] = css; g_cst[t] = cst;
        float ts = g_tcolsum[t]; if (ts == 0.f) ts = 100.f;
        g_invts[t] = m / ts;
    }
    if (t == 0) {
        double sumL2 = sred[0];
        double bw = sumL2 / ((double)NTOT * (double)NTOT - (double)NTOT);
        bw = bw / 4.0;
        for (int i = 0; i < 5; i++)
            g_c[i] = (float)(-1.4426950408889634 / (bw * (double)(1 << i)));
        double p = (double)curr_iter[0] / 1000.0;
        g_lamb = (float)(2.0 / (1.0 + exp(-p)) - 1.0);
    }
}

// ---------------- masked normalized target logits (widened) ----------------
__global__ void k_u(const float* __restrict__ logits) {
    int i = blockIdx.x * blockDim.x + threadIdx.x;
    if (i >= B_ROWS) return;
    #pragma unroll
    for (int c = 0; c < NCLS; c++)
        g_u[i * 32 + c] = logits[(size_t)i * NCLS + c] * g_invts[c];
    g_u[i * 32 + 31] = 0.f;
}

// ---------------- precompute TT weight tiles (fp32): scale * U U^T ---------
__global__ __launch_bounds__(256, 2)
void k_wtt() {
    __shared__ float Us[128][33];
    __shared__ float Ut[128][33];
    int bid = blockIdx.x;     // tri index
    int r = 0, b = bid;
    while (b >= NT - r) { b -= NT - r; r++; }
    int ti = r, tj = r + b;
    int gi0 = ti * 128, gj0 = tj * 128;
    int t = threadIdx.x;
    int tx = t & 15, ty = t >> 4;

    for (int idx = t; idx < 4096; idx += 256) {
        int row = idx >> 5, c = idx & 31;
        Us[row][c] = g_u[(size_t)(gi0 + row) * 32 + c];
        Ut[row][c] = g_u[(size_t)(gj0 + row) * 32 + c];
    }
    __syncthreads();

    float acc[8][8];
    #pragma unroll
    for (int i = 0; i < 8; i++)
        #pragma unroll
        for (int j = 0; j < 8; j++) acc[i][j] = 0.f;

    #pragma unroll 1
    for (int c = 0; c < NCLS; c++) {
        float a[8], bb[8];
        #pragma unroll
        for (int i = 0; i < 8; i++) a[i] = Us[ty * 8 + i][c];
        #pragma unroll
        for (int j = 0; j < 8; j++) bb[j] = Ut[tx * 8 + j][c];
        #pragma unroll
        for (int i = 0; i < 8; i++)
            #pragma unroll
            for (int j = 0; j < 8; j++)
                acc[i][j] = fmaf(a[i], bb[j], acc[i][j]);
    }

    float scale = g_scale;
    float* W = g_wtt + (size_t)bid * 16384;
    #pragma unroll
    for (int i = 0; i < 8; i++) {
        int il = ty * 8 + i;
        float4 v0 = make_float4(acc[i][0]*scale, acc[i][1]*scale, acc[i][2]*scale, acc[i][3]*scale);
        float4 v1 = make_float4(acc[i][4]*scale, acc[i][5]*scale, acc[i][6]*scale, acc[i][7]*scale);
        *(float4*)(W + il * 128 + tx * 8 + 0) = v0;
        *(float4*)(W + il * 128 + tx * 8 + 4) = v1;
    }
}

// ---------------- helpers ----------------
__device__ __forceinline__ float ex2f(float x) {
    float r; asm("ex2.approx.ftz.f32 %0, %1;" : "=f"(r) : "f"(x)); return r;
}
__device__ __forceinline__ uint32_t smem_u32(const void* p) {
    uint32_t a;
    asm("{ .reg .u64 t; cvta.to.shared.u64 t, %1; cvt.u32.u64 %0, t; }" : "=r"(a) : "l"(p));
    return a;
}
__device__ __forceinline__ void cp16(uint32_t dst, const void* src) {
    asm volatile("cp.async.cg.shared.global [%0], [%1], 16;" :: "r"(dst), "l"(src) : "memory");
}
#define CP_COMMIT() asm volatile("cp.async.commit_group;" ::: "memory")
#define CP_WAIT(n)  asm volatile("cp.async.wait_group %0;" :: "n"(n) : "memory")

#define LDSM4(r, addr) \
    asm volatile("ldmatrix.sync.aligned.m8n8.x4.shared.b16 {%0,%1,%2,%3}, [%4];" \
        : "=r"((r)[0]), "=r"((r)[1]), "=r"((r)[2]), "=r"((r)[3]) : "r"(addr))

#define MMA16816(d, a, b0_, b1_) \
    asm volatile("mma.sync.aligned.m16n8k16.row.col.f32.bf16.bf16.f32 " \
        "{%0,%1,%2,%3},{%4,%5,%6,%7},{%8,%9},{%0,%1,%2,%3};" \
        : "+f"((d)[0]), "+f"((d)[1]), "+f"((d)[2]), "+f"((d)[3]) \
        : "r"((a)[0]), "r"((a)[1]), "r"((a)[2]), "r"((a)[3]), "r"(b0_), "r"(b1_))

// XOR swizzle for 64B rows of 4x16B units
__device__ __forceinline__ uint32_t swz(int row, int j) {
    return (uint32_t)(row * 64 + ((j ^ ((row ^ (row >> 2)) & 3)) << 4));
}

// dynamic smem layout
#define SM_STAGES   0u          // 2 stages x 4 matrices x 8192B = 65536
#define SM_SQI      65536u
#define SM_SQJ      66048u
#define SM_LI       66560u
#define SM_LJ       67072u
#define SM_CSS      67584u
#define SM_CST      67712u
#define SM_UJT      67840u      // 32 x 128 floats = 16384
#define SM_TOTAL    84224u

// ---------------- main: bf16 mma.sync Gram + fused epilogue ----------------
__global__ __launch_bounds__(256, 2)
void k_main(const int* __restrict__ slabel) {
    extern __shared__ char smem[];
    uint32_t sb = smem_u32(smem);
    int t = threadIdx.x;
    int w = t >> 5, lane = t & 31;

    // tile decode
    int bid = blockIdx.x;
    int type, ti, tj, triq = 0;
    if (bid < TRI) { type = 0; }
    else if (bid < 2 * TRI) { type = 1; bid -= TRI; }
    else { type = 2; bid -= 2 * TRI; }
    if (type < 2) {
        int r = 0, b = bid;
        while (b >= NT - r) { b -= NT - r; r++; }
        ti = r; tj = r + b; triq = bid;
    } else { ti = bid >> 5; tj = bid & 31; }

    int gi0 = ti * 128, gj0 = tj * 128;
    int rowA0 = ((type == 1) ? B_ROWS : 0) + gi0;
    int rowB0 = ((type == 0) ? 0 : B_ROWS) + gj0;

    const char* bAh = (const char*)g_hi + (size_t)rowA0 * 1024;
    const char* bAl = (const char*)g_lo + (size_t)rowA0 * 1024;
    const char* bBh = (const char*)g_hi + (size_t)rowB0 * 1024;
    const char* bBl = (const char*)g_lo + (size_t)rowB0 * 1024;

    // ---- issue chunk 0 ----
    {
        uint32_t stb = sb + SM_STAGES;
        #pragma unroll
        for (int i = 0; i < 8; i++) {
            const int mat = i >> 1;
            int rem = (i & 1) * 256 + t;
            int row = rem >> 2, j = rem & 3;
            const char* srcB = (mat == 0) ? bAh : (mat == 1) ? bAl : (mat == 2) ? bBh : bBl;
            cp16(stb + mat * 8192 + swz(row, j), srcB + (size_t)row * 1024 + j * 16);
        }
        CP_COMMIT();
    }

    // ---- epilogue tables ----
    float* sqI = (float*)(smem + SM_SQI);
    float* sqJ = (float*)(smem + SM_SQJ);
    int*   Li  = (int*)(smem + SM_LI);
    int*   Lj  = (int*)(smem + SM_LJ);
    float* css = (float*)(smem + SM_CSS);
    float* cst = (float*)(smem + SM_CST);
    float* UjT = (float*)(smem + SM_UJT);   // [32][128]

    if (t < 128) {
        sqI[t] = g_sq[rowA0 + t];
        sqJ[t] = g_sq[rowB0 + t];
        Li[t] = (type != 1) ? slabel[gi0 + t] : 0;
        Lj[t] = (type == 0) ? slabel[gj0 + t] : 0;
    }
    if (t < NCLS) { css[t] = g_css[t]; cst[t] = g_cst[t]; }
    if (type == 2) {
        for (int idx = t; idx < 4096; idx += 256) {
            int c = idx >> 7, j = idx & 127;
            UjT[c * 128 + j] = g_u[(size_t)(gj0 + j) * 32 + c];
        }
    }

    // warp tiling: 4 x 2 warps, each 32(m) x 64(n)
    int m_base = (w & 3) * 32;
    int n_base = (w >> 2) * 64;
    int arow = (lane & 7) + 8 * ((lane >> 3) & 1);
    int brow = (lane & 7) + 8 * (lane >> 4);
    int aj0 = (lane >> 4);
    int bj0 = ((lane >> 3) & 1);

    float acc[2][8][4];
    #pragma unroll
    for (int mi = 0; mi < 2; mi++)
        #pragma unroll
        for (int nt = 0; nt < 8; nt++)
            #pragma unroll
            for (int e = 0; e < 4; e++) acc[mi][nt][e] = 0.f;

    // ---- mainloop: 16 chunks of k=32, double buffered ----
    #pragma unroll 1
    for (int c = 0; c < 16; c++) {
        int s = c & 1;
        if (c < 15) {
            uint32_t stb = sb + SM_STAGES + (s ^ 1) * 32768;
            int koff = (c + 1) * 64;
            #pragma unroll
            for (int i = 0; i < 8; i++) {
                const int mat = i >> 1;
                int rem = (i & 1) * 256 + t;
                int row = rem >> 2, j = rem & 3;
                const char* srcB = (mat == 0) ? bAh : (mat == 1) ? bAl : (mat == 2) ? bBh : bBl;
                cp16(stb + mat * 8192 + swz(row, j), srcB + (size_t)row * 1024 + koff + j * 16);
            }
            CP_COMMIT();
            CP_WAIT(1);
        } else {
            CP_WAIT(0);
        }
        __syncthreads();

        uint32_t stb = sb + SM_STAGES + s * 32768;
        #pragma unroll
        for (int h = 0; h < 2; h++) {
            uint32_t Ah[2][4], Al[2][4];
            #pragma unroll
            for (int mi = 0; mi < 2; mi++) {
                int rA = m_base + mi * 16 + arow;
                uint32_t off = swz(rA, 2 * h + aj0);
                LDSM4(Ah[mi], stb + 0 * 8192 + off);
                LDSM4(Al[mi], stb + 1 * 8192 + off);
            }
            #pragma unroll
            for (int p = 0; p < 4; p++) {
                int rB = n_base + p * 16 + brow;
                uint32_t off = swz(rB, 2 * h + bj0);
                uint32_t Bh[4], Bl[4];
                LDSM4(Bh, stb + 2 * 8192 + off);
                LDSM4(Bl, stb + 3 * 8192 + off);
                #pragma unroll
                for (int mi = 0; mi < 2; mi++) {
                    MMA16816(acc[mi][2 * p + 0], Ah[mi], Bh[0], Bh[1]);
                    MMA16816(acc[mi][2 * p + 1], Ah[mi], Bh[2], Bh[3]);
                    MMA16816(acc[mi][2 * p + 0], Ah[mi], Bl[0], Bl[1]);
                    MMA16816(acc[mi][2 * p + 1], Ah[mi], Bl[2], Bl[3]);
                    MMA16816(acc[mi][2 * p + 0], Al[mi], Bh[0], Bh[1]);
                    MMA16816(acc[mi][2 * p + 1], Al[mi], Bh[2], Bh[3]);
                }
            }
        }
        __syncthreads();
    }

    // ---- epilogue ----
    float c4 = g_c[4];
    float part = 0.f;
    int r0 = m_base + (lane >> 2);
    int c0 = n_base + 2 * (lane & 3);
    const float* Wt = g_wtt + (size_t)triq * 16384;

    #pragma unroll
    for (int mi = 0; mi < 2; mi++) {
        #pragma unroll
        for (int half = 0; half < 2; half++) {
            int r = r0 + mi * 16 + half * 8;
            float si = sqI[r];
            int li = Li[r];
            float wss = css[li];
            float wst = cst[li];
            const float* ujrow = UjT + li * 128;
            #pragma unroll
            for (int nt = 0; nt < 8; nt++) {
                int cc = c0 + nt * 8;
                float d0 = acc[mi][nt][half * 2 + 0];
                float d1 = acc[mi][nt][half * 2 + 1];
                float w0, w1;
                if (type == 0) {
                    w0 = (li == Lj[cc]) ? wss : 0.f;
                    w1 = (li == Lj[cc + 1]) ? wss : 0.f;
                } else if (type == 1) {
                    float2 wv = *(const float2*)(Wt + r * 128 + cc);
                    w0 = wv.x; w1 = wv.y;
                } else {
                    w0 = wst * ujrow[cc];
                    w1 = wst * ujrow[cc + 1];
                }
                float L2a = fmaxf(fmaf(-2.f, d0, si + sqJ[cc]), 0.f);
                float L2b = fmaxf(fmaf(-2.f, d1, si + sqJ[cc + 1]), 0.f);
                float ea4 = ex2f(L2a * c4);
                float eb4 = ex2f(L2b * c4);
                float ea3 = ea4 * ea4, ea2 = ea3 * ea3, ea1 = ea2 * ea2, ea0 = ea1 * ea1;
                float eb3 = eb4 * eb4, eb2 = eb3 * eb3, eb1 = eb2 * eb2, eb0 = eb1 * eb1;
                float ksa = ((ea0 + ea1) + (ea2 + ea3)) + ea4;
                float ksb = ((eb0 + eb1) + (eb2 + eb3)) + eb4;
                part = fmaf(w0, ksa, part);
                part = fmaf(w1, ksb, part);
            }
        }
    }

    #pragma unroll
    for (int o = 16; o; o >>= 1) part += __shfl_xor_sync(0xffffffffu, part, o);
    if (lane == 0) {
        double f = (type < 2 && ti != tj) ? 2.0 : 1.0;
        atomicAdd(&g_acc[type], f * (double)part);
    }
}

// ---------------- output ----------------
__global__ void k_out(float* out) {
    out[0] = (float)(g_lamb * (g_acc[0] + g_acc[1] - 2.0 * g_acc[2]));
}

extern "C" void kernel_launch(void* const* d_in, const int* in_sizes, int n_in,
                              void* d_out, int out_size) {
    const float* src    = (const float*)d_in[0];
    const float* tgt    = (const float*)d_in[1];
    const int*   lbl    = (const int*)d_in[2];
    const float* logits = (const float*)d_in[3];
    const int*   iter   = (const int*)d_in[4];
    float* out = (float*)d_out;

    cudaFuncSetAttribute(k_main, cudaFuncAttributeMaxDynamicSharedMemorySize, SM_TOTAL);

    k_split<<<(NTOT * DIM / 4) / 256, 256>>>(src, tgt);
    k_colsum<<<256, 512>>>(src, tgt);
    k_stats<<<32, 128>>>(lbl, logits);
    k_finalize<<<1, 512>>>(iter);
    k_u<<<32, 128>>>(logits);
    k_wtt<<<TRI, 256>>>();
    k_main<<<2 * TRI + NT * NT, 256, SM_TOTAL>>>(lbl);
    k_out<<<1, 1>>>(out);
}

// round 12
// speedup vs baseline: 3.1752x; 1.0166x over previous
#include <cuda_runtime.h>
#include <cuda_bf16.h>
#include <math.h>
#include <stdint.h>

#define B_ROWS 4096
#define DIM    512
#define NCLS   31
#define NTOT   8192
#define NT     32        // 4096/128 tiles per side
#define TRI    528       // NT*(NT+1)/2
#define GRID_MAIN (2 * TRI + NT * NT)

typedef unsigned long long ull;

// ---------------- device scratch ----------------
__device__ double g_acc[3];
__device__ double g_sumsq;
__device__ unsigned g_done;
__device__ float  g_S[DIM];
__device__ float  g_sq[NTOT];
__device__ int    g_scount[NCLS];
__device__ int    g_tcount[NCLS];
__device__ float  g_tcolsum[NCLS];
__device__ float  g_css[NCLS];
__device__ float  g_cst[NCLS];
__device__ float  g_invts[NCLS];
__device__ __align__(16) float g_u[B_ROWS * 32];
__device__ float  g_c[5];
__device__ float  g_scale;
__device__ float  g_lamb;
// bf16 split of concat(source,target): 8192 x 512 each
__device__ __align__(16) __nv_bfloat16 g_hi[NTOT * DIM];
__device__ __align__(16) __nv_bfloat16 g_lo[NTOT * DIM];
// precomputed TT weights (fp32), upper-triangle tiles
__device__ __align__(16) float g_wtt[TRI * 128 * 128];

// ---------------- bf16 hi/lo split + fused row sq-norms + init ----------------
__global__ void k_split(const float* __restrict__ src, const float* __restrict__ tgt) {
    __shared__ float part[8];
    int t = threadIdx.x;
    int idx = blockIdx.x * blockDim.x + t;   // float4 index
    int lane = t & 31, w = t >> 5;
    int e = idx * 4;
    int row = e >> 9;     // block covers 1024 floats = rows 2b, 2b+1
    const float* base = (row < B_ROWS) ? src : (tgt - (size_t)B_ROWS * DIM);
    float4 v = *(const float4*)(base + e);
    __nv_bfloat16 h0 = __float2bfloat16(v.x);
    __nv_bfloat16 h1 = __float2bfloat16(v.y);
    __nv_bfloat16 h2 = __float2bfloat16(v.z);
    __nv_bfloat16 h3 = __float2bfloat16(v.w);
    __nv_bfloat16 l0 = __float2bfloat16(v.x - __bfloat162float(h0));
    __nv_bfloat16 l1 = __float2bfloat16(v.y - __bfloat162float(h1));
    __nv_bfloat16 l2 = __float2bfloat16(v.z - __bfloat162float(h2));
    __nv_bfloat16 l3 = __float2bfloat16(v.w - __bfloat162float(h3));
    __nv_bfloat162* H = (__nv_bfloat162*)g_hi;
    __nv_bfloat162* L = (__nv_bfloat162*)g_lo;
    H[idx * 2 + 0] = __nv_bfloat162(h0, h1);
    H[idx * 2 + 1] = __nv_bfloat162(h2, h3);
    L[idx * 2 + 0] = __nv_bfloat162(l0, l1);
    L[idx * 2 + 1] = __nv_bfloat162(l2, l3);
    // row squared-norm: warps 0-3 -> row 2b, warps 4-7 -> row 2b+1 (no atomics)
    float s = fmaf(v.x, v.x, fmaf(v.y, v.y, fmaf(v.z, v.z, v.w * v.w)));
    #pragma unroll
    for (int o = 16; o; o >>= 1) s += __shfl_xor_sync(0xffffffffu, s, o);
    if (lane == 0) part[w] = s;
    __syncthreads();
    if (t < 2) {
        float r = part[t * 4] + part[t * 4 + 1] + part[t * 4 + 2] + part[t * 4 + 3];
        g_sq[blockIdx.x * 2 + t] = r;
    }
    // fold init (kernel boundary orders this before all atomics users)
    if (blockIdx.x == 0) {
        if (t < 3) g_acc[t] = 0.0;
        if (t == 3) g_sumsq = 0.0;
        if (t == 4) g_done = 0u;
        if (t < NCLS) { g_scount[t] = 0; g_tcount[t] = 0; g_tcolsum[t] = 0.f; }
        g_S[t] = 0.f; g_S[t + 256] = 0.f;
    }
}

// ---------------- column sums + total sum of squares ----------------
__global__ void k_colsum(const float* __restrict__ src, const float* __restrict__ tgt) {
    __shared__ float s2p[16];
    int d = threadIdx.x;   // 512 threads
    int b = blockIdx.x;    // 256 blocks, 16 rows each per array
    int lane = d & 31, w = d >> 5;
    float s = 0.f, s2 = 0.f;
    int r0 = b * 16;
    for (int r = r0; r < r0 + 16; r++) {
        float a = src[(size_t)r * DIM + d];
        float c = tgt[(size_t)r * DIM + d];
        s += a + c;
        s2 = fmaf(a, a, fmaf(c, c, s2));
    }
    atomicAdd(&g_S[d], s);
    #pragma unroll
    for (int o = 16; o; o >>= 1) s2 += __shfl_xor_sync(0xffffffffu, s2, o);
    if (lane == 0) s2p[w] = s2;
    __syncthreads();
    if (d == 0) {
        float tot = 0.f;
        #pragma unroll
        for (int i = 0; i < 16; i++) tot += s2p[i];
        atomicAdd(&g_sumsq, (double)tot);
    }
}

// ---------------- class stats ----------------
__global__ void k_stats(const int* __restrict__ lbl, const float* __restrict__ logits) {
    int b = blockIdx.x;
    int t = threadIdx.x;
    int i = b * 128 + t;
    atomicAdd(&g_scount[lbl[i]], 1);
    const float* row = logits + (size_t)i * NCLS;
    float mv = row[0]; int mi = 0;
    #pragma unroll
    for (int c = 1; c < NCLS; c++) { float v = row[c]; if (v > mv) { mv = v; mi = c; } }
    atomicAdd(&g_tcount[mi], 1);
    if (t < NCLS) {
        float s = 0.f;
        for (int r = 0; r < 128; r++) s += logits[(size_t)(b * 128 + r) * NCLS + t];
        atomicAdd(&g_tcolsum[t], s);
    }
}

// ---------------- finalize (short critical path now) ----------------
__global__ void k_finalize(const int* __restrict__ curr_iter) {
    __shared__ double sred[512];
    __shared__ float  sm[NCLS];
    __shared__ float  sscale;
    int t = threadIdx.x;  // 512 threads
    double Sv = (double)g_S[t];
    sred[t] = -2.0 * Sv * Sv;
    __syncthreads();
    for (int o = 256; o; o >>= 1) { if (t < o) sred[t] += sred[t + o]; __syncthreads(); }
    if (t < NCLS) sm[t] = (g_scount[t] > 0 && g_tcount[t] > 0) ? 1.f : 0.f;
    __syncthreads();
    if (t == 0) {
        float cnt = 0.f;
        for (int c = 0; c < NCLS; c++) cnt += sm[c];
        sscale = (cnt > 0.f) ? 1.f / fmaxf(cnt, 1.f) : 0.f;
        g_scale = sscale;
    }
    __syncthreads();
    if (t < NCLS) {
        float m = sm[t];
        int sc = g_scount[t];
        float css = 0.f, cst = 0.f;
        if (sc > 0) { float fc = (float)sc; css = m * sscale / (fc * fc); cst = m * sscale / fc; }
        g_css[t] = css; g_cst[t] = cst;
        float ts = g_tcolsum[t]; if (ts == 0.f) ts = 100.f;
        g_invts[t] = m / ts;
    }
    if (t == 0) {
        double sumL2 = 2.0 * (double)NTOT * g_sumsq + sred[0];
        double bw = sumL2 / ((double)NTOT * (double)NTOT - (double)NTOT);
        bw = bw / 4.0;
        for (int i = 0; i < 5; i++)
            g_c[i] = (float)(-1.4426950408889634 / (bw * (double)(1 << i)));
        double p = (double)curr_iter[0] / 1000.0;
        g_lamb = (float)(2.0 / (1.0 + exp(-p)) - 1.0);
    }
}

// ---------------- masked normalized target logits ----------------
__global__ void k_u(const float* __restrict__ logits) {
    int i = blockIdx.x * blockDim.x + threadIdx.x;
    if (i >= B_ROWS) return;
    #pragma unroll
    for (int c = 0; c < NCLS; c++)
        g_u[i * 32 + c] = logits[(size_t)i * NCLS + c] * g_invts[c];
    g_u[i * 32 + 31] = 0.f;
}

// ---------------- precompute TT weight tiles (fp32): scale * U U^T ---------
__global__ __launch_bounds__(256, 2)
void k_wtt() {
    __shared__ float Us[128][33];
    __shared__ float Ut[128][33];
    int bid = blockIdx.x;     // tri index
    int r = 0, b = bid;
    while (b >= NT - r) { b -= NT - r; r++; }
    int ti = r, tj = r + b;
    int gi0 = ti * 128, gj0 = tj * 128;
    int t = threadIdx.x;
    int tx = t & 15, ty = t >> 4;

    for (int idx = t; idx < 4096; idx += 256) {
        int row = idx >> 5, c = idx & 31;
        Us[row][c] = g_u[(size_t)(gi0 + row) * 32 + c];
        Ut[row][c] = g_u[(size_t)(gj0 + row) * 32 + c];
    }
    __syncthreads();

    float acc[8][8];
    #pragma unroll
    for (int i = 0; i < 8; i++)
        #pragma unroll
        for (int j = 0; j < 8; j++) acc[i][j] = 0.f;

    #pragma unroll 1
    for (int c = 0; c < NCLS; c++) {
        float a[8], bb[8];
        #pragma unroll
        for (int i = 0; i < 8; i++) a[i] = Us[ty * 8 + i][c];
        #pragma unroll
        for (int j = 0; j < 8; j++) bb[j] = Ut[tx * 8 + j][c];
        #pragma unroll
        for (int i = 0; i < 8; i++)
            #pragma unroll
            for (int j = 0; j < 8; j++)
                acc[i][j] = fmaf(a[i], bb[j], acc[i][j]);
    }

    float scale = g_scale;
    float* W = g_wtt + (size_t)bid * 16384;
    #pragma unroll
    for (int i = 0; i < 8; i++) {
        int il = ty * 8 + i;
        float4 v0 = make_float4(acc[i][0]*scale, acc[i][1]*scale, acc[i][2]*scale, acc[i][3]*scale);
        float4 v1 = make_float4(acc[i][4]*scale, acc[i][5]*scale, acc[i][6]*scale, acc[i][7]*scale);
        *(float4*)(W + il * 128 + tx * 8 + 0) = v0;
        *(float4*)(W + il * 128 + tx * 8 + 4) = v1;
    }
}

// ---------------- helpers ----------------
__device__ __forceinline__ float ex2f(float x) {
    float r; asm("ex2.approx.ftz.f32 %0, %1;" : "=f"(r) : "f"(x)); return r;
}
__device__ __forceinline__ uint32_t smem_u32(const void* p) {
    uint32_t a;
    asm("{ .reg .u64 t; cvta.to.shared.u64 t, %1; cvt.u32.u64 %0, t; }" : "=r"(a) : "l"(p));
    return a;
}
__device__ __forceinline__ void cp16(uint32_t dst, const void* src) {
    asm volatile("cp.async.cg.shared.global [%0], [%1], 16;" :: "r"(dst), "l"(src) : "memory");
}
#define CP_COMMIT() asm volatile("cp.async.commit_group;" ::: "memory")
#define CP_WAIT(n)  asm volatile("cp.async.wait_group %0;" :: "n"(n) : "memory")

#define LDSM4(r, addr) \
    asm volatile("ldmatrix.sync.aligned.m8n8.x4.shared.b16 {%0,%1,%2,%3}, [%4];" \
        : "=r"((r)[0]), "=r"((r)[1]), "=r"((r)[2]), "=r"((r)[3]) : "r"(addr))

#define MMA16816(d, a, b0_, b1_) \
    asm volatile("mma.sync.aligned.m16n8k16.row.col.f32.bf16.bf16.f32 " \
        "{%0,%1,%2,%3},{%4,%5,%6,%7},{%8,%9},{%0,%1,%2,%3};" \
        : "+f"((d)[0]), "+f"((d)[1]), "+f"((d)[2]), "+f"((d)[3]) \
        : "r"((a)[0]), "r"((a)[1]), "r"((a)[2]), "r"((a)[3]), "r"(b0_), "r"(b1_))

// XOR swizzle for 64B rows of 4x16B units
__device__ __forceinline__ uint32_t swz(int row, int j) {
    return (uint32_t)(row * 64 + ((j ^ ((row ^ (row >> 2)) & 3)) << 4));
}

// dynamic smem layout
#define SM_STAGES   0u          // 2 stages x 4 matrices x 8192B = 65536
#define SM_SQI      65536u
#define SM_SQJ      66048u
#define SM_LI       66560u
#define SM_LJ       67072u
#define SM_CSS      67584u
#define SM_CST      67712u
#define SM_UJT      67840u      // 32 x 128 floats = 16384
#define SM_TOTAL    84224u

// ---------------- main: bf16 mma.sync Gram + fused epilogue + final out ----
__global__ __launch_bounds__(256, 2)
void k_main(const int* __restrict__ slabel, float* __restrict__ out) {
    extern __shared__ char smem[];
    uint32_t sb = smem_u32(smem);
    int t = threadIdx.x;
    int w = t >> 5, lane = t & 31;

    // tile decode
    int bid = blockIdx.x;
    int type, ti, tj, triq = 0;
    if (bid < TRI) { type = 0; }
    else if (bid < 2 * TRI) { type = 1; bid -= TRI; }
    else { type = 2; bid -= 2 * TRI; }
    if (type < 2) {
        int r = 0, b = bid;
        while (b >= NT - r) { b -= NT - r; r++; }
        ti = r; tj = r + b; triq = bid;
    } else { ti = bid >> 5; tj = bid & 31; }

    int gi0 = ti * 128, gj0 = tj * 128;
    int rowA0 = ((type == 1) ? B_ROWS : 0) + gi0;
    int rowB0 = ((type == 0) ? 0 : B_ROWS) + gj0;

    const char* bAh = (const char*)g_hi + (size_t)rowA0 * 1024;
    const char* bAl = (const char*)g_lo + (size_t)rowA0 * 1024;
    const char* bBh = (const char*)g_hi + (size_t)rowB0 * 1024;
    const char* bBl = (const char*)g_lo + (size_t)rowB0 * 1024;

    // ---- issue chunk 0 ----
    {
        uint32_t stb = sb + SM_STAGES;
        #pragma unroll
        for (int i = 0; i < 8; i++) {
            const int mat = i >> 1;
            int rem = (i & 1) * 256 + t;
            int row = rem >> 2, j = rem & 3;
            const char* srcB = (mat == 0) ? bAh : (mat == 1) ? bAl : (mat == 2) ? bBh : bBl;
            cp16(stb + mat * 8192 + swz(row, j), srcB + (size_t)row * 1024 + j * 16);
        }
        CP_COMMIT();
    }

    // ---- epilogue tables ----
    float* sqI = (float*)(smem + SM_SQI);
    float* sqJ = (float*)(smem + SM_SQJ);
    int*   Li  = (int*)(smem + SM_LI);
    int*   Lj  = (int*)(smem + SM_LJ);
    float* css = (float*)(smem + SM_CSS);
    float* cst = (float*)(smem + SM_CST);
    float* UjT = (float*)(smem + SM_UJT);   // [32][128]

    if (t < 128) {
        sqI[t] = g_sq[rowA0 + t];
        sqJ[t] = g_sq[rowB0 + t];
        Li[t] = (type != 1) ? slabel[gi0 + t] : 0;
        Lj[t] = (type == 0) ? slabel[gj0 + t] : 0;
    }
    if (t < NCLS) { css[t] = g_css[t]; cst[t] = g_cst[t]; }
    if (type == 2) {
        for (int idx = t; idx < 4096; idx += 256) {
            int c = idx >> 7, j = idx & 127;
            UjT[c * 128 + j] = g_u[(size_t)(gj0 + j) * 32 + c];
        }
    }

    // warp tiling: 4 x 2 warps, each 32(m) x 64(n)
    int m_base = (w & 3) * 32;
    int n_base = (w >> 2) * 64;
    int arow = (lane & 7) + 8 * ((lane >> 3) & 1);
    int brow = (lane & 7) + 8 * (lane >> 4);
    int aj0 = (lane >> 4);
    int bj0 = ((lane >> 3) & 1);

    float acc[2][8][4];
    #pragma unroll
    for (int mi = 0; mi < 2; mi++)
        #pragma unroll
        for (int nt = 0; nt < 8; nt++)
            #pragma unroll
            for (int e = 0; e < 4; e++) acc[mi][nt][e] = 0.f;

    // ---- mainloop: 16 chunks of k=32, double buffered ----
    #pragma unroll 1
    for (int c = 0; c < 16; c++) {
        int s = c & 1;
        if (c < 15) {
            uint32_t stb = sb + SM_STAGES + (s ^ 1) * 32768;
            int koff = (c + 1) * 64;
            #pragma unroll
            for (int i = 0; i < 8; i++) {
                const int mat = i >> 1;
                int rem = (i & 1) * 256 + t;
                int row = rem >> 2, j = rem & 3;
                const char* srcB = (mat == 0) ? bAh : (mat == 1) ? bAl : (mat == 2) ? bBh : bBl;
                cp16(stb + mat * 8192 + swz(row, j), srcB + (size_t)row * 1024 + koff + j * 16);
            }
            CP_COMMIT();
            CP_WAIT(1);
        } else {
            CP_WAIT(0);
        }
        __syncthreads();

        uint32_t stb = sb + SM_STAGES + s * 32768;
        #pragma unroll
        for (int h = 0; h < 2; h++) {
            uint32_t Ah[2][4], Al[2][4];
            #pragma unroll
            for (int mi = 0; mi < 2; mi++) {
                int rA = m_base + mi * 16 + arow;
                uint32_t off = swz(rA, 2 * h + aj0);
                LDSM4(Ah[mi], stb + 0 * 8192 + off);
                LDSM4(Al[mi], stb + 1 * 8192 + off);
            }
            #pragma unroll
            for (int p = 0; p < 4; p++) {
                int rB = n_base + p * 16 + brow;
                uint32_t off = swz(rB, 2 * h + bj0);
                uint32_t Bh[4], Bl[4];
                LDSM4(Bh, stb + 2 * 8192 + off);
                LDSM4(Bl, stb + 3 * 8192 + off);
                #pragma unroll
                for (int mi = 0; mi < 2; mi++) {
                    MMA16816(acc[mi][2 * p + 0], Ah[mi], Bh[0], Bh[1]);
                    MMA16816(acc[mi][2 * p + 1], Ah[mi], Bh[2], Bh[3]);
                    MMA16816(acc[mi][2 * p + 0], Ah[mi], Bl[0], Bl[1]);
                    MMA16816(acc[mi][2 * p + 1], Ah[mi], Bl[2], Bl[3]);
                    MMA16816(acc[mi][2 * p + 0], Al[mi], Bh[0], Bh[1]);
                    MMA16816(acc[mi][2 * p + 1], Al[mi], Bh[2], Bh[3]);
                }
            }
        }
        __syncthreads();
    }

    // ---- epilogue ----
    float c4 = g_c[4];
    float part = 0.f;
    int r0 = m_base + (lane >> 2);
    int c0 = n_base + 2 * (lane & 3);
    const float* Wt = g_wtt + (size_t)triq * 16384;

    #pragma unroll
    for (int mi = 0; mi < 2; mi++) {
        #pragma unroll
        for (int half = 0; half < 2; half++) {
            int r = r0 + mi * 16 + half * 8;
            float si = sqI[r];
            int li = Li[r];
            float wss = css[li];
            float wst = cst[li];
            const float* ujrow = UjT + li * 128;
            #pragma unroll
            for (int nt = 0; nt < 8; nt++) {
                int cc = c0 + nt * 8;
                float d0 = acc[mi][nt][half * 2 + 0];
                float d1 = acc[mi][nt][half * 2 + 1];
                float w0, w1;
                if (type == 0) {
                    w0 = (li == Lj[cc]) ? wss : 0.f;
                    w1 = (li == Lj[cc + 1]) ? wss : 0.f;
                } else if (type == 1) {
                    float2 wv = *(const float2*)(Wt + r * 128 + cc);
                    w0 = wv.x; w1 = wv.y;
                } else {
                    w0 = wst * ujrow[cc];
                    w1 = wst * ujrow[cc + 1];
                }
                float L2a = fmaxf(fmaf(-2.f, d0, si + sqJ[cc]), 0.f);
                float L2b = fmaxf(fmaf(-2.f, d1, si + sqJ[cc + 1]), 0.f);
                float ea4 = ex2f(L2a * c4);
                float eb4 = ex2f(L2b * c4);
                float ea3 = ea4 * ea4, ea2 = ea3 * ea3, ea1 = ea2 * ea2, ea0 = ea1 * ea1;
                float eb3 = eb4 * eb4, eb2 = eb3 * eb3, eb1 = eb2 * eb2, eb0 = eb1 * eb1;
                float ksa = ((ea0 + ea1) + (ea2 + ea3)) + ea4;
                float ksb = ((eb0 + eb1) + (eb2 + eb3)) + eb4;
                part = fmaf(w0, ksa, part);
                part = fmaf(w1, ksb, part);
            }
        }
    }

    #pragma unroll
    for (int o = 16; o; o >>= 1) part += __shfl_xor_sync(0xffffffffu, part, o);
    if (lane == 0) {
        double f = (type < 2 && ti != tj) ? 2.0 : 1.0;
        atomicAdd(&g_acc[type], f * (double)part);
    }
    // last finished block writes the final output (replaces k_out launch)
    __syncthreads();
    if (t == 0) {
        __threadfence();
        unsigned v = atomicAdd(&g_done, 1u);
        if (v == GRID_MAIN - 1) {
            out[0] = (float)(g_lamb * (g_acc[0] + g_acc[1] - 2.0 * g_acc[2]));
        }
    }
}

extern "C" void kernel_launch(void* const* d_in, const int* in_sizes, int n_in,
                              void* d_out, int out_size) {
    const float* src    = (const float*)d_in[0];
    const float* tgt    = (const float*)d_in[1];
    const int*   lbl    = (const int*)d_in[2];
    const float* logits = (const float*)d_in[3];
    const int*   iter   = (const int*)d_in[4];
    float* out = (float*)d_out;

    cudaFuncSetAttribute(k_main, cudaFuncAttributeMaxDynamicSharedMemorySize, SM_TOTAL);

    k_split<<<(NTOT * DIM / 4) / 256, 256>>>(src, tgt);
    k_colsum<<<256, 512>>>(src, tgt);
    k_stats<<<32, 128>>>(lbl, logits);
    k_finalize<<<1, 512>>>(iter);
    k_u<<<32, 128>>>(logits);
    k_wtt<<<TRI, 256>>>();
    k_main<<<GRID_MAIN, 256, SM_TOTAL>>>(lbl, out);
}

// round 15
// speedup vs baseline: 3.2487x; 1.0232x over previous
#include <cuda_runtime.h>
#include <cuda_bf16.h>
#include <math.h>
#include <stdint.h>

#define B_ROWS 4096
#define DIM    512
#define NCLS   31
#define NTOT   8192
#define NT     32        // 4096/128 tiles per side
#define TRI    528       // NT*(NT+1)/2
#define GRID_MAIN (2 * TRI + NT * NT)

typedef unsigned long long ull;

// ---------------- device scratch ----------------
__device__ double g_acc[3];
__device__ double g_sumsq;
__device__ unsigned g_done;
__device__ float  g_S[DIM];
__device__ float  g_sq[NTOT];
__device__ int    g_scount[NCLS];
__device__ int    g_tcount[NCLS];
__device__ float  g_tcolsum[NCLS];
__device__ float  g_css[NCLS];
__device__ float  g_cst[NCLS];
__device__ float  g_invts[NCLS];
__device__ float  g_c[5];
__device__ float  g_scale;
__device__ float  g_lamb;
// bf16 split of concat(source,target): 8192 x 512 each
__device__ __align__(16) __nv_bfloat16 g_hi[NTOT * DIM];
__device__ __align__(16) __nv_bfloat16 g_lo[NTOT * DIM];
// precomputed TT weights (fp32), upper-triangle tiles
__device__ __align__(16) float g_wtt[TRI * 128 * 128];

// ---------------- bf16 hi/lo split + fused row sq-norms + init ----------------
__global__ void k_split(const float* __restrict__ src, const float* __restrict__ tgt) {
    __shared__ float part[8];
    int t = threadIdx.x;
    int idx = blockIdx.x * blockDim.x + t;   // float4 index
    int lane = t & 31, w = t >> 5;
    int e = idx * 4;
    int row = e >> 9;     // block covers 1024 floats = rows 2b, 2b+1
    const float* base = (row < B_ROWS) ? src : (tgt - (size_t)B_ROWS * DIM);
    float4 v = *(const float4*)(base + e);
    __nv_bfloat16 h0 = __float2bfloat16(v.x);
    __nv_bfloat16 h1 = __float2bfloat16(v.y);
    __nv_bfloat16 h2 = __float2bfloat16(v.z);
    __nv_bfloat16 h3 = __float2bfloat16(v.w);
    __nv_bfloat16 l0 = __float2bfloat16(v.x - __bfloat162float(h0));
    __nv_bfloat16 l1 = __float2bfloat16(v.y - __bfloat162float(h1));
    __nv_bfloat16 l2 = __float2bfloat16(v.z - __bfloat162float(h2));
    __nv_bfloat16 l3 = __float2bfloat16(v.w - __bfloat162float(h3));
    __nv_bfloat162* H = (__nv_bfloat162*)g_hi;
    __nv_bfloat162* L = (__nv_bfloat162*)g_lo;
    H[idx * 2 + 0] = __nv_bfloat162(h0, h1);
    H[idx * 2 + 1] = __nv_bfloat162(h2, h3);
    L[idx * 2 + 0] = __nv_bfloat162(l0, l1);
    L[idx * 2 + 1] = __nv_bfloat162(l2, l3);
    // row squared-norm: warps 0-3 -> row 2b, warps 4-7 -> row 2b+1 (no atomics)
    float s = fmaf(v.x, v.x, fmaf(v.y, v.y, fmaf(v.z, v.z, v.w * v.w)));
    #pragma unroll
    for (int o = 16; o; o >>= 1) s += __shfl_xor_sync(0xffffffffu, s, o);
    if (lane == 0) part[w] = s;
    __syncthreads();
    if (t < 2) {
        float r = part[t * 4] + part[t * 4 + 1] + part[t * 4 + 2] + part[t * 4 + 3];
        g_sq[blockIdx.x * 2 + t] = r;
    }
    // fold init (kernel boundary orders this before all atomics users)
    if (blockIdx.x == 0) {
        if (t < 3) g_acc[t] = 0.0;
        if (t == 3) g_sumsq = 0.0;
        if (t == 4) g_done = 0u;
        if (t < NCLS) { g_scount[t] = 0; g_tcount[t] = 0; g_tcolsum[t] = 0.f; }
        g_S[t] = 0.f; g_S[t + 256] = 0.f;
    }
}

// ---------------- column sums + total sum of squares ----------------
__global__ void k_colsum(const float* __restrict__ src, const float* __restrict__ tgt) {
    __shared__ float s2p[16];
    int d = threadIdx.x;   // 512 threads
    int b = blockIdx.x;    // 256 blocks, 16 rows each per array
    int lane = d & 31, w = d >> 5;
    float s = 0.f, s2 = 0.f;
    int r0 = b * 16;
    for (int r = r0; r < r0 + 16; r++) {
        float a = src[(size_t)r * DIM + d];
        float c = tgt[(size_t)r * DIM + d];
        s += a + c;
        s2 = fmaf(a, a, fmaf(c, c, s2));
    }
    atomicAdd(&g_S[d], s);
    #pragma unroll
    for (int o = 16; o; o >>= 1) s2 += __shfl_xor_sync(0xffffffffu, s2, o);
    if (lane == 0) s2p[w] = s2;
    __syncthreads();
    if (d == 0) {
        float tot = 0.f;
        #pragma unroll
        for (int i = 0; i < 16; i++) tot += s2p[i];
        atomicAdd(&g_sumsq, (double)tot);
    }
}

// ---------------- class stats ----------------
__global__ void k_stats(const int* __restrict__ lbl, const float* __restrict__ logits) {
    int b = blockIdx.x;
    int t = threadIdx.x;
    int i = b * 128 + t;
    atomicAdd(&g_scount[lbl[i]], 1);
    const float* row = logits + (size_t)i * NCLS;
    float mv = row[0]; int mi = 0;
    #pragma unroll
    for (int c = 1; c < NCLS; c++) { float v = row[c]; if (v > mv) { mv = v; mi = c; } }
    atomicAdd(&g_tcount[mi], 1);
    if (t < NCLS) {
        float s = 0.f;
        for (int r = 0; r < 128; r++) s += logits[(size_t)(b * 128 + r) * NCLS + t];
        atomicAdd(&g_tcolsum[t], s);
    }
}

// ---------------- finalize: single warp, no barriers ----------------
__global__ void k_finalize(const int* __restrict__ curr_iter) {
    int lane = threadIdx.x;   // 32 threads
    // sum of S^2 over 512 columns (16 per lane, MLP-overlapped)
    double s2 = 0.0;
    #pragma unroll
    for (int i = 0; i < 16; i++) {
        double Sv = (double)g_S[lane + i * 32];
        s2 += Sv * Sv;
    }
    #pragma unroll
    for (int o = 16; o; o >>= 1)
        s2 += __shfl_xor_sync(0xffffffffu, s2, o);
    // class mask + count
    float m = 0.f;
    int sc = 0;
    if (lane < NCLS) {
        sc = g_scount[lane];
        m = (sc > 0 && g_tcount[lane] > 0) ? 1.f : 0.f;
    }
    float cnt = m;
    #pragma unroll
    for (int o = 16; o; o >>= 1) cnt += __shfl_xor_sync(0xffffffffu, cnt, o);
    float sscale = (cnt > 0.f) ? 1.f / fmaxf(cnt, 1.f) : 0.f;
    if (lane == 0) g_scale = sscale;
    if (lane < NCLS) {
        float css = 0.f, cst = 0.f;
        if (sc > 0) { float fc = (float)sc; css = m * sscale / (fc * fc); cst = m * sscale / fc; }
        g_css[lane] = css; g_cst[lane] = cst;
        float ts = g_tcolsum[lane]; if (ts == 0.f) ts = 100.f;
        g_invts[lane] = m / ts;
    }
    if (lane == 0) {
        double sumL2 = 2.0 * (double)NTOT * g_sumsq - 2.0 * s2;
        double bw = sumL2 / ((double)NTOT * (double)NTOT - (double)NTOT);
        bw = bw / 4.0;
        for (int i = 0; i < 5; i++)
            g_c[i] = (float)(-1.4426950408889634 / (bw * (double)(1 << i)));
        double p = (double)curr_iter[0] / 1000.0;
        g_lamb = (float)(2.0 / (1.0 + exp(-p)) - 1.0);
    }
}

// ---------------- precompute TT weight tiles (fp32): scale * U U^T ---------
// U built on the fly: U[i][c] = logits[i][c] * invts[c]
__global__ __launch_bounds__(256, 2)
void k_wtt(const float* __restrict__ logits) {
    __shared__ float Us[128][33];
    __shared__ float Ut[128][33];
    int bid = blockIdx.x;     // tri index
    int r = 0, b = bid;
    while (b >= NT - r) { b -= NT - r; r++; }
    int ti = r, tj = r + b;
    int gi0 = ti * 128, gj0 = tj * 128;
    int t = threadIdx.x;
    int tx = t & 15, ty = t >> 4;

    for (int idx = t; idx < 4096; idx += 256) {
        int row = idx >> 5, c = idx & 31;
        float iv = (c < NCLS) ? g_invts[c] : 0.f;
        Us[row][c] = (c < NCLS) ? logits[(size_t)(gi0 + row) * NCLS + c] * iv : 0.f;
        Ut[row][c] = (c < NCLS) ? logits[(size_t)(gj0 + row) * NCLS + c] * iv : 0.f;
    }
    __syncthreads();

    float acc[8][8];
    #pragma unroll
    for (int i = 0; i < 8; i++)
        #pragma unroll
        for (int j = 0; j < 8; j++) acc[i][j] = 0.f;

    #pragma unroll 1
    for (int c = 0; c < NCLS; c++) {
        float a[8], bb[8];
        #pragma unroll
        for (int i = 0; i < 8; i++) a[i] = Us[ty * 8 + i][c];
        #pragma unroll
        for (int j = 0; j < 8; j++) bb[j] = Ut[tx * 8 + j][c];
        #pragma unroll
        for (int i = 0; i < 8; i++)
            #pragma unroll
            for (int j = 0; j < 8; j++)
                acc[i][j] = fmaf(a[i], bb[j], acc[i][j]);
    }

    float scale = g_scale;
    float* W = g_wtt + (size_t)bid * 16384;
    #pragma unroll
    for (int i = 0; i < 8; i++) {
        int il = ty * 8 + i;
        float4 v0 = make_float4(acc[i][0]*scale, acc[i][1]*scale, acc[i][2]*scale, acc[i][3]*scale);
        float4 v1 = make_float4(acc[i][4]*scale, acc[i][5]*scale, acc[i][6]*scale, acc[i][7]*scale);
        *(float4*)(W + il * 128 + tx * 8 + 0) = v0;
        *(float4*)(W + il * 128 + tx * 8 + 4) = v1;
    }
}

// ---------------- helpers ----------------
__device__ __forceinline__ float ex2f(float x) {
    float r; asm("ex2.approx.ftz.f32 %0, %1;" : "=f"(r) : "f"(x)); return r;
}
__device__ __forceinline__ uint32_t smem_u32(const void* p) {
    uint32_t a;
    asm("{ .reg .u64 t; cvta.to.shared.u64 t, %1; cvt.u32.u64 %0, t; }" : "=r"(a) : "l"(p));
    return a;
}
__device__ __forceinline__ void cp16(uint32_t dst, const void* src) {
    asm volatile("cp.async.cg.shared.global [%0], [%1], 16;" :: "r"(dst), "l"(src) : "memory");
}
#define CP_COMMIT() asm volatile("cp.async.commit_group;" ::: "memory")
#define CP_WAIT(n)  asm volatile("cp.async.wait_group %0;" :: "n"(n) : "memory")

#define LDSM4(r, addr) \
    asm volatile("ldmatrix.sync.aligned.m8n8.x4.shared.b16 {%0,%1,%2,%3}, [%4];" \
        : "=r"((r)[0]), "=r"((r)[1]), "=r"((r)[2]), "=r"((r)[3]) : "r"(addr))

#define MMA16816(d, a, b0_, b1_) \
    asm volatile("mma.sync.aligned.m16n8k16.row.col.f32.bf16.bf16.f32 " \
        "{%0,%1,%2,%3},{%4,%5,%6,%7},{%8,%9},{%0,%1,%2,%3};" \
        : "+f"((d)[0]), "+f"((d)[1]), "+f"((d)[2]), "+f"((d)[3]) \
        : "r"((a)[0]), "r"((a)[1]), "r"((a)[2]), "r"((a)[3]), "r"(b0_), "r"(b1_))

// XOR swizzle for 64B rows of 4x16B units
__device__ __forceinline__ uint32_t swz(int row, int j) {
    return (uint32_t)(row * 64 + ((j ^ ((row ^ (row >> 2)) & 3)) << 4));
}

// dynamic smem layout
#define SM_STAGES   0u          // 2 stages x 4 matrices x 8192B = 65536
#define SM_SQI      65536u
#define SM_SQJ      66048u
#define SM_LI       66560u
#define SM_LJ       67072u
#define SM_CSS      67584u
#define SM_CST      67712u
#define SM_UJT      67840u      // 32 x 128 floats = 16384
#define SM_TOTAL    84224u

// ---------------- main: bf16 mma.sync Gram + fused epilogue + final out ----
__global__ __launch_bounds__(256, 2)
void k_main(const int* __restrict__ slabel, const float* __restrict__ logits,
            float* __restrict__ out) {
    extern __shared__ char smem[];
    uint32_t sb = smem_u32(smem);
    int t = threadIdx.x;
    int w = t >> 5, lane = t & 31;

    // tile decode
    int bid = blockIdx.x;
    int type, ti, tj, triq = 0;
    if (bid < TRI) { type = 0; }
    else if (bid < 2 * TRI) { type = 1; bid -= TRI; }
    else { type = 2; bid -= 2 * TRI; }
    if (type < 2) {
        int r = 0, b = bid;
        while (b >= NT - r) { b -= NT - r; r++; }
        ti = r; tj = r + b; triq = bid;
    } else { ti = bid >> 5; tj = bid & 31; }

    int gi0 = ti * 128, gj0 = tj * 128;
    int rowA0 = ((type == 1) ? B_ROWS : 0) + gi0;
    int rowB0 = ((type == 0) ? 0 : B_ROWS) + gj0;

    const char* bAh = (const char*)g_hi + (size_t)rowA0 * 1024;
    const char* bAl = (const char*)g_lo + (size_t)rowA0 * 1024;
    const char* bBh = (const char*)g_hi + (size_t)rowB0 * 1024;
    const char* bBl = (const char*)g_lo + (size_t)rowB0 * 1024;

    // ---- issue chunk 0 ----
    {
        uint32_t stb = sb + SM_STAGES;
        #pragma unroll
        for (int i = 0; i < 8; i++) {
            const int mat = i >> 1;
            int rem = (i & 1) * 256 + t;
            int row = rem >> 2, j = rem & 3;
            const char* srcB = (mat == 0) ? bAh : (mat == 1) ? bAl : (mat == 2) ? bBh : bBl;
            cp16(stb + mat * 8192 + swz(row, j), srcB + (size_t)row * 1024 + j * 16);
        }
        CP_COMMIT();
    }

    // ---- epilogue tables ----
    float* sqI = (float*)(smem + SM_SQI);
    float* sqJ = (float*)(smem + SM_SQJ);
    int*   Li  = (int*)(smem + SM_LI);
    int*   Lj  = (int*)(smem + SM_LJ);
    float* css = (float*)(smem + SM_CSS);
    float* cst = (float*)(smem + SM_CST);
    float* UjT = (float*)(smem + SM_UJT);   // [32][128]

    if (t < 128) {
        sqI[t] = g_sq[rowA0 + t];
        sqJ[t] = g_sq[rowB0 + t];
        Li[t] = (type != 1) ? slabel[gi0 + t] : 0;
        Lj[t] = (type == 0) ? slabel[gj0 + t] : 0;
    }
    if (t < NCLS) { css[t] = g_css[t]; cst[t] = g_cst[t]; }
    if (type == 2) {
        for (int idx = t; idx < 4096; idx += 256) {
            int c = idx >> 7, j = idx & 127;
            UjT[c * 128 + j] = (c < NCLS)
                ? logits[(size_t)(gj0 + j) * NCLS + c] * g_invts[c] : 0.f;
        }
    }

    // warp tiling: 4 x 2 warps, each 32(m) x 64(n)
    int m_base = (w & 3) * 32;
    int n_base = (w >> 2) * 64;
    int arow = (lane & 7) + 8 * ((lane >> 3) & 1);
    int brow = (lane & 7) + 8 * (lane >> 4);
    int aj0 = (lane >> 4);
    int bj0 = ((lane >> 3) & 1);

    float acc[2][8][4];
    #pragma unroll
    for (int mi = 0; mi < 2; mi++)
        #pragma unroll
        for (int nt = 0; nt < 8; nt++)
            #pragma unroll
            for (int e = 0; e < 4; e++) acc[mi][nt][e] = 0.f;

    // ---- mainloop: 16 chunks of k=32, double buffered ----
    #pragma unroll 1
    for (int c = 0; c < 16; c++) {
        int s = c & 1;
        if (c < 15) {
            uint32_t stb = sb + SM_STAGES + (s ^ 1) * 32768;
            int koff = (c + 1) * 64;
            #pragma unroll
            for (int i = 0; i < 8; i++) {
                const int mat = i >> 1;
                int rem = (i & 1) * 256 + t;
                int row = rem >> 2, j = rem & 3;
                const char* srcB = (mat == 0) ? bAh : (mat == 1) ? bAl : (mat == 2) ? bBh : bBl;
                cp16(stb + mat * 8192 + swz(row, j), srcB + (size_t)row * 1024 + koff + j * 16);
            }
            CP_COMMIT();
            CP_WAIT(1);
        } else {
            CP_WAIT(0);
        }
        __syncthreads();

        uint32_t stb = sb + SM_STAGES + s * 32768;
        #pragma unroll
        for (int h = 0; h < 2; h++) {
            uint32_t Ah[2][4], Al[2][4];
            #pragma unroll
            for (int mi = 0; mi < 2; mi++) {
                int rA = m_base + mi * 16 + arow;
                uint32_t off = swz(rA, 2 * h + aj0);
                LDSM4(Ah[mi], stb + 0 * 8192 + off);
                LDSM4(Al[mi], stb + 1 * 8192 + off);
            }
            #pragma unroll
            for (int p = 0; p < 4; p++) {
                int rB = n_base + p * 16 + brow;
                uint32_t off = swz(rB, 2 * h + bj0);
                uint32_t Bh[4], Bl[4];
                LDSM4(Bh, stb + 2 * 8192 + off);
                LDSM4(Bl, stb + 3 * 8192 + off);
                #pragma unroll
                for (int mi = 0; mi < 2; mi++) {
                    MMA16816(acc[mi][2 * p + 0], Ah[mi], Bh[0], Bh[1]);
                    MMA16816(acc[mi][2 * p + 1], Ah[mi], Bh[2], Bh[3]);
                    MMA16816(acc[mi][2 * p + 0], Ah[mi], Bl[0], Bl[1]);
                    MMA16816(acc[mi][2 * p + 1], Ah[mi], Bl[2], Bl[3]);
                    MMA16816(acc[mi][2 * p + 0], Al[mi], Bh[0], Bh[1]);
                    MMA16816(acc[mi][2 * p + 1], Al[mi], Bh[2], Bh[3]);
                }
            }
        }
        __syncthreads();
    }

    // ---- epilogue ----
    float c4 = g_c[4];
    float part = 0.f;
    int r0 = m_base + (lane >> 2);
    int c0 = n_base + 2 * (lane & 3);
    const float* Wt = g_wtt + (size_t)triq * 16384;

    #pragma unroll
    for (int mi = 0; mi < 2; mi++) {
        #pragma unroll
        for (int half = 0; half < 2; half++) {
            int r = r0 + mi * 16 + half * 8;
            float si = sqI[r];
            int li = Li[r];
            float wss = css[li];
            float wst = cst[li];
            const float* ujrow = UjT + li * 128;
            #pragma unroll
            for (int nt = 0; nt < 8; nt++) {
                int cc = c0 + nt * 8;
                float d0 = acc[mi][nt][half * 2 + 0];
                float d1 = acc[mi][nt][half * 2 + 1];
                float w0, w1;
                if (type == 0) {
                    w0 = (li == Lj[cc]) ? wss : 0.f;
                    w1 = (li == Lj[cc + 1]) ? wss : 0.f;
                } else if (type == 1) {
                    float2 wv = *(const float2*)(Wt + r * 128 + cc);
                    w0 = wv.x; w1 = wv.y;
                } else {
                    w0 = wst * ujrow[cc];
                    w1 = wst * ujrow[cc + 1];
                }
                float L2a = fmaxf(fmaf(-2.f, d0, si + sqJ[cc]), 0.f);
                float L2b = fmaxf(fmaf(-2.f, d1, si + sqJ[cc + 1]), 0.f);
                float ea4 = ex2f(L2a * c4);
                float eb4 = ex2f(L2b * c4);
                float ea3 = ea4 * ea4, ea2 = ea3 * ea3, ea1 = ea2 * ea2, ea0 = ea1 * ea1;
                float eb3 = eb4 * eb4, eb2 = eb3 * eb3, eb1 = eb2 * eb2, eb0 = eb1 * eb1;
                float ksa = ((ea0 + ea1) + (ea2 + ea3)) + ea4;
                float ksb = ((eb0 + eb1) + (eb2 + eb3)) + eb4;
                part = fmaf(w0, ksa, part);
                part = fmaf(w1, ksb, part);
            }
        }
    }

    #pragma unroll
    for (int o = 16; o; o >>= 1) part += __shfl_xor_sync(0xffffffffu, part, o);
    if (lane == 0) {
        double f = (type < 2 && ti != tj) ? 2.0 : 1.0;
        atomicAdd(&g_acc[type], f * (double)part);
    }
    // last finished block writes the final output
    __syncthreads();
    if (t == 0) {
        __threadfence();
        unsigned v = atomicAdd(&g_done, 1u);
        if (v == GRID_MAIN - 1) {
            out[0] = (float)(g_lamb * (g_acc[0] + g_acc[1] - 2.0 * g_acc[2]));
        }
    }
}

extern "C" void kernel_launch(void* const* d_in, const int* in_sizes, int n_in,
                              void* d_out, int out_size) {
    const float* src    = (const float*)d_in[0];
    const float* tgt    = (const float*)d_in[1];
    const int*   lbl    = (const int*)d_in[2];
    const float* logits = (const float*)d_in[3];
    const int*   iter   = (const int*)d_in[4];
    float* out = (float*)d_out;

    cudaFuncSetAttribute(k_main, cudaFuncAttributeMaxDynamicSharedMemorySize, SM_TOTAL);

    k_split<<<(NTOT * DIM / 4) / 256, 256>>>(src, tgt);
    k_colsum<<<256, 512>>>(src, tgt);
    k_stats<<<32, 128>>>(lbl, logits);
    k_finalize<<<1, 32>>>(iter);
    k_wtt<<<TRI, 256>>>(logits);
    k_main<<<GRID_MAIN, 256, SM_TOTAL>>>(lbl, logits, out);
}